// round 2
// baseline (speedup 1.0000x reference)
#include <cuda_runtime.h>
#include <math.h>

#define N_CLASS 32000
#define NH      1024
#define ENC     512
#define DEC     256

// ---------------- scratch (no allocations allowed) ----------------
__device__ float g_xw_enc[ENC * NH];       // enc input projections
__device__ float g_enc_out[ENC * NH];      // encoder hidden states (also the h chain)
__device__ float g_A[ENC * NH];            // attn(enc_outputs)
__device__ float g_xw_dec[DEC * NH];       // dec input projections
__device__ float g_hcat[DEC * 2 * NH];     // [h_t ; context_t] rows for the batched out GEMM
__device__ float g_scores[ENC];            // per-step attention scores (reused -> ldcg)
__device__ float g_h0[NH];                 // initial hidden
__device__ unsigned g_bar_enc;
__device__ unsigned g_bar_dec;

__global__ void init_kernel(const float* __restrict__ hidden) {
    int i = blockIdx.x * blockDim.x + threadIdx.x;
    if (i == 0) { g_bar_enc = 0u; g_bar_dec = 0u; }
    if (i < NH) g_h0[i] = hidden[i];
}

// ---------------- generic fp32 GEMM: C[M,N] = A[M,K] @ B[N,K]^T + bias[N] ----------------
// BM=BN=64, BK=16, 256 threads, 4x4 per thread, register-prefetch software pipeline.
__global__ void __launch_bounds__(256) gemm_bias_kernel(
    const float* __restrict__ Am, const float* __restrict__ Bm,
    const float* __restrict__ bias, float* __restrict__ Cm,
    int M, int N, int K)
{
    __shared__ float As[16][68];
    __shared__ float Bs[16][68];

    const int tid = threadIdx.x;
    const int tx  = tid & 15;        // N direction (4 cols each)
    const int ty  = tid >> 4;        // M direction (4 rows each)
    const int m0  = blockIdx.y * 64;
    const int n0  = blockIdx.x * 64;
    const int lr  = tid >> 2;        // 0..63 tile row for loads
    const int lc4 = (tid & 3) * 4;   // 0,4,8,12 k-offset for loads

    const float* aptr = Am + (size_t)(m0 + lr) * K + lc4;
    const float* bptr = Bm + (size_t)(n0 + lr) * K + lc4;

    float acc[4][4];
    #pragma unroll
    for (int i = 0; i < 4; i++)
        #pragma unroll
        for (int j = 0; j < 4; j++) acc[i][j] = 0.f;

    float4 av = *(const float4*)(aptr);
    float4 bv = *(const float4*)(bptr);

    for (int k0 = 0; k0 < K; k0 += 16) {
        As[lc4 + 0][lr] = av.x; As[lc4 + 1][lr] = av.y;
        As[lc4 + 2][lr] = av.z; As[lc4 + 3][lr] = av.w;
        Bs[lc4 + 0][lr] = bv.x; Bs[lc4 + 1][lr] = bv.y;
        Bs[lc4 + 2][lr] = bv.z; Bs[lc4 + 3][lr] = bv.w;
        __syncthreads();

        int kn = k0 + 16;
        if (kn < K) {   // prefetch next tile while computing this one
            av = *(const float4*)(aptr + kn);
            bv = *(const float4*)(bptr + kn);
        }

        #pragma unroll
        for (int kk = 0; kk < 16; kk++) {
            float4 a4 = *(const float4*)&As[kk][ty * 4];
            float4 b4 = *(const float4*)&Bs[kk][tx * 4];
            float a[4] = {a4.x, a4.y, a4.z, a4.w};
            float b[4] = {b4.x, b4.y, b4.z, b4.w};
            #pragma unroll
            for (int i = 0; i < 4; i++)
                #pragma unroll
                for (int j = 0; j < 4; j++)
                    acc[i][j] = fmaf(a[i], b[j], acc[i][j]);
        }
        __syncthreads();
    }

    #pragma unroll
    for (int i = 0; i < 4; i++) {
        #pragma unroll
        for (int j = 0; j < 4; j++) {
            int n = n0 + tx * 4 + j;
            Cm[(size_t)(m0 + ty * 4 + i) * N + n] = acc[i][j] + bias[n];
        }
    }
}

// ---------------- encoder scan: 512 sequential steps, 32 CTAs x 512 threads ----------------
// CTA c owns rows [32c, 32c+32) of W_hh, register-resident (64 floats/thread).
// thread: row = 32c + tid/16, k-chunk = (tid%16)*64.
__global__ void __launch_bounds__(512, 1) enc_scan_kernel(
    const float* __restrict__ Whh, const float* __restrict__ bhh)
{
    const int c     = blockIdx.x;
    const int tid   = threadIdx.x;
    const int row   = c * 32 + (tid >> 4);
    const int chunk = tid & 15;

    float w[64];
    {
        const float* wp = Whh + (size_t)row * NH + chunk * 64;
        #pragma unroll
        for (int i = 0; i < 64; i++) w[i] = wp[i];
    }
    const float bias = bhh[row];

    __shared__ float sh[NH];
    unsigned target = 0;

    for (int t = 0; t < ENC; t++) {
        const float* hp = (t == 0) ? g_h0 : (g_enc_out + (size_t)(t - 1) * NH);
        if (tid < NH / 4) {
            float4 v = __ldcg((const float4*)hp + tid);
            *(float4*)&sh[tid * 4] = v;
        }
        __syncthreads();

        float acc = 0.f;
        #pragma unroll
        for (int i = 0; i < 16; i++) {
            float4 hv = *(const float4*)&sh[chunk * 64 + i * 4];
            acc = fmaf(w[4 * i + 0], hv.x, acc);
            acc = fmaf(w[4 * i + 1], hv.y, acc);
            acc = fmaf(w[4 * i + 2], hv.z, acc);
            acc = fmaf(w[4 * i + 3], hv.w, acc);
        }
        #pragma unroll
        for (int o = 8; o > 0; o >>= 1) acc += __shfl_xor_sync(0xffffffffu, acc, o);

        if (chunk == 0) {
            float z = acc + g_xw_enc[(size_t)t * NH + row] + bias;
            g_enc_out[(size_t)t * NH + row] = tanhf(z);
            __threadfence();
        }
        __syncthreads();
        target += 32;
        if (tid == 0) {
            atomicAdd(&g_bar_enc, 1u);
            while (*((volatile unsigned*)&g_bar_enc) < target) { }
        }
        __syncthreads();
    }
}

// ---------------- decoder scan: 256 steps, 32 CTAs x 512 threads, 2 barriers/step ----------------
__global__ void __launch_bounds__(512, 1) dec_scan_kernel(
    const float* __restrict__ Whh, const float* __restrict__ bhh,
    const float* __restrict__ A, float* __restrict__ attns)
{
    const int c     = blockIdx.x;
    const int tid   = threadIdx.x;
    const int row   = c * 32 + (tid >> 4);
    const int chunk = tid & 15;

    float w[64];
    {
        const float* wp = Whh + (size_t)row * NH + chunk * 64;
        #pragma unroll
        for (int i = 0; i < 64; i++) w[i] = wp[i];
    }
    const float bias = bhh[row];

    __shared__ float sh[NH];
    __shared__ float sw[ENC];
    __shared__ float red[512];
    __shared__ float cred[16][33];
    unsigned target = 0;

    for (int t = 0; t < DEC; t++) {
        // -------- phase 1: h_new = tanh(xw_t + W_hh @ h_prev + b) --------
        const float* hp = (t == 0) ? (g_enc_out + (size_t)(ENC - 1) * NH)
                                   : (g_hcat + (size_t)(t - 1) * 2 * NH);
        if (tid < NH / 4) {
            float4 v = __ldcg((const float4*)hp + tid);
            *(float4*)&sh[tid * 4] = v;
        }
        __syncthreads();

        float acc = 0.f;
        #pragma unroll
        for (int i = 0; i < 16; i++) {
            float4 hv = *(const float4*)&sh[chunk * 64 + i * 4];
            acc = fmaf(w[4 * i + 0], hv.x, acc);
            acc = fmaf(w[4 * i + 1], hv.y, acc);
            acc = fmaf(w[4 * i + 2], hv.z, acc);
            acc = fmaf(w[4 * i + 3], hv.w, acc);
        }
        #pragma unroll
        for (int o = 8; o > 0; o >>= 1) acc += __shfl_xor_sync(0xffffffffu, acc, o);
        if (chunk == 0) {
            float z = acc + g_xw_dec[(size_t)t * NH + row] + bias;
            g_hcat[(size_t)t * 2 * NH + row] = tanhf(z);
            __threadfence();
        }
        __syncthreads();
        target += 32;
        if (tid == 0) {
            atomicAdd(&g_bar_dec, 1u);
            while (*((volatile unsigned*)&g_bar_dec) < target) { }
        }
        __syncthreads();

        // -------- phase 2: scores = A @ h_new, 16 scores per CTA (1 warp each) --------
        if (tid < NH / 4) {
            float4 v = __ldcg((const float4*)(g_hcat + (size_t)t * 2 * NH) + tid);
            *(float4*)&sh[tid * 4] = v;
        }
        __syncthreads();
        {
            int warp = tid >> 5, lane = tid & 31;
            int sr = c * 16 + warp;
            const float* ar = A + (size_t)sr * NH;
            float sacc = 0.f;
            #pragma unroll
            for (int i = 0; i < 32; i++)
                sacc = fmaf(ar[lane + 32 * i], sh[lane + 32 * i], sacc);
            #pragma unroll
            for (int o = 16; o > 0; o >>= 1) sacc += __shfl_xor_sync(0xffffffffu, sacc, o);
            if (lane == 0) { g_scores[sr] = sacc; __threadfence(); }
        }
        __syncthreads();
        target += 32;
        if (tid == 0) {
            atomicAdd(&g_bar_dec, 1u);
            while (*((volatile unsigned*)&g_bar_dec) < target) { }
        }
        __syncthreads();

        // -------- phase 3: softmax (redundant per CTA) + context --------
        float s = __ldcg(&g_scores[tid]);   // ENC == 512 == blockDim
        red[tid] = s;
        __syncthreads();
        #pragma unroll
        for (int o = 256; o > 0; o >>= 1) {
            if (tid < o) red[tid] = fmaxf(red[tid], red[tid + o]);
            __syncthreads();
        }
        float smax = red[0];
        __syncthreads();
        float e = expf(s - smax);
        red[tid] = e;
        __syncthreads();
        #pragma unroll
        for (int o = 256; o > 0; o >>= 1) {
            if (tid < o) red[tid] += red[tid + o];
            __syncthreads();
        }
        float wgt = e / red[0];
        sw[tid] = wgt;
        if (c == 0) attns[(size_t)t * ENC + tid] = wgt;
        __syncthreads();

        // context[j] = sum_i w_i * enc_out[i][j], CTA owns cols [32c, 32c+32)
        {
            int g = tid >> 5, j = tid & 31;
            int col = c * 32 + j;
            float ca = 0.f;
            #pragma unroll
            for (int ii = 0; ii < 32; ii++) {
                int i = g * 32 + ii;
                ca = fmaf(sw[i], g_enc_out[(size_t)i * NH + col], ca);
            }
            cred[g][j] = ca;
            __syncthreads();
            if (tid < 32) {
                float cs = 0.f;
                #pragma unroll
                for (int g2 = 0; g2 < 16; g2++) cs += cred[g2][tid];
                g_hcat[(size_t)t * 2 * NH + NH + c * 32 + tid] = cs;
            }
        }
        __syncthreads();
    }
}

// ---------------- launch ----------------
extern "C" void kernel_launch(void* const* d_in, const int* in_sizes, int n_in,
                              void* d_out, int out_size)
{
    const float* enc_input = (const float*)d_in[0];
    const float* hidden    = (const float*)d_in[1];
    const float* dec_input = (const float*)d_in[2];
    const float* enc_W_ih  = (const float*)d_in[3];
    const float* enc_W_hh  = (const float*)d_in[4];
    const float* enc_b_ih  = (const float*)d_in[5];
    const float* enc_b_hh  = (const float*)d_in[6];
    const float* dec_W_ih  = (const float*)d_in[7];
    const float* dec_W_hh  = (const float*)d_in[8];
    const float* dec_b_ih  = (const float*)d_in[9];
    const float* dec_b_hh  = (const float*)d_in[10];
    const float* attn_W    = (const float*)d_in[11];
    const float* attn_b    = (const float*)d_in[12];
    const float* out_W     = (const float*)d_in[13];
    const float* out_b     = (const float*)d_in[14];

    float* out   = (float*)d_out;
    float* outs  = out;                              // [256, 32000]
    float* attns = out + (size_t)DEC * N_CLASS;      // [256, 512]

    float *p_xw_enc, *p_enc_out, *p_A, *p_xw_dec, *p_hcat;
    cudaGetSymbolAddress((void**)&p_xw_enc, g_xw_enc);
    cudaGetSymbolAddress((void**)&p_enc_out, g_enc_out);
    cudaGetSymbolAddress((void**)&p_A, g_A);
    cudaGetSymbolAddress((void**)&p_xw_dec, g_xw_dec);
    cudaGetSymbolAddress((void**)&p_hcat, g_hcat);

    // reset barriers + stage h0
    init_kernel<<<4, 256>>>(hidden);

    // enc_xw = enc_input @ enc_W_ih^T + b_ih        [512,1024] K=32000
    gemm_bias_kernel<<<dim3(NH / 64, ENC / 64), 256>>>(
        enc_input, enc_W_ih, enc_b_ih, p_xw_enc, ENC, NH, N_CLASS);

    // sequential encoder scan -> g_enc_out
    enc_scan_kernel<<<32, 512>>>(enc_W_hh, enc_b_hh);

    // A = enc_out @ attn_W^T + attn_b               [512,1024] K=1024
    gemm_bias_kernel<<<dim3(NH / 64, ENC / 64), 256>>>(
        p_enc_out, attn_W, attn_b, p_A, ENC, NH, NH);

    // dec_xw = dec_input @ dec_W_ih^T + b_ih        [256,1024] K=32000
    gemm_bias_kernel<<<dim3(NH / 64, DEC / 64), 256>>>(
        dec_input, dec_W_ih, dec_b_ih, p_xw_dec, DEC, NH, N_CLASS);

    // sequential decoder scan -> g_hcat rows + attns
    dec_scan_kernel<<<32, 512>>>(dec_W_hh, dec_b_hh, p_A, attns);

    // outs = hcat @ out_W^T + out_b                 [256,32000] K=2048 (batched!)
    gemm_bias_kernel<<<dim3(N_CLASS / 64, DEC / 64), 256>>>(
        p_hcat, out_W, out_b, outs, DEC, N_CLASS, 2 * NH);
}

// round 5
// speedup vs baseline: 1.9846x; 1.9846x over previous
#include <cuda_runtime.h>
#include <math.h>

#define N_CLASS 32000
#define NH      1024
#define ENC     512
#define DEC     256

// ---------------- scratch ----------------
__device__ float g_xw_enc[ENC * NH];
__device__ float g_enc_out[ENC * NH];
__device__ float g_A[ENC * NH];
__device__ float g_xw_dec[DEC * NH];
__device__ float g_hcat[DEC * 2 * NH];
__device__ float g_scores[ENC];
__device__ float g_h0[NH];
__device__ float g_part[16 * 256 * 1024];   // split-K partials (max 4.2M floats)
__device__ unsigned g_bar_enc;
__device__ unsigned g_bar_dec;

__global__ void init_kernel(const float* __restrict__ hidden) {
    int i = blockIdx.x * blockDim.x + threadIdx.x;
    if (i == 0) { g_bar_enc = 0u; g_bar_dec = 0u; }
    if (i < NH) g_h0[i] = hidden[i];
}

// ---------------- helpers ----------------
__device__ __forceinline__ float tanh_fast(float x) {
    float e = __expf(2.f * x);
    return 1.f - 2.f / (e + 1.f);
}

// grid-wide barrier: caller must __syncthreads() BEFORE calling.
__device__ __forceinline__ void grid_bar(unsigned* ctr, unsigned target, int tid) {
    if (tid == 0) {
        asm volatile("red.release.gpu.global.add.u32 [%0], 1;" :: "l"(ctr) : "memory");
        unsigned v;
        do {
            asm volatile("ld.acquire.gpu.global.u32 %0, [%1];" : "=r"(v) : "l"(ctr) : "memory");
        } while (v < target);
    }
    __syncthreads();
}

// ---------------- GEMM: C[M,N] = A[M,K] @ B[N,K]^T (+bias if single split) ----------------
// 128x128x8 tile, 256 threads, 8x8 microtile, split-K via blockIdx.z.
#define BM 128
#define BN 128
#define BK 8
#define BPAD 4

__global__ void __launch_bounds__(256, 2) gemm_splitk(
    const float* __restrict__ Am, const float* __restrict__ Bm,
    const float* __restrict__ bias, float* __restrict__ Cdirect,
    float* __restrict__ partial,
    int M, int N, int K, int kchunk)
{
    __shared__ float As[BK][BM + BPAD];
    __shared__ float Bs[BK][BN + BPAD];

    const int tid = threadIdx.x;
    const int m0 = blockIdx.y * BM;
    const int n0 = blockIdx.x * BN;
    const int s  = blockIdx.z;
    const int k0 = s * kchunk;

    const int lr = tid >> 1;          // 0..127
    const int lk = (tid & 1) * 4;     // 0 or 4

    const float* ap = Am + (size_t)(m0 + lr) * K + k0 + lk;
    const float* bp = Bm + (size_t)(n0 + lr) * K + k0 + lk;

    const int tx = tid & 15;          // N dir
    const int ty = tid >> 4;          // M dir

    float acc[8][8];
    #pragma unroll
    for (int i = 0; i < 8; i++)
        #pragma unroll
        for (int j = 0; j < 8; j++) acc[i][j] = 0.f;

    float4 av = *(const float4*)ap;
    float4 bv = *(const float4*)bp;

    for (int kt = 0; kt < kchunk; kt += BK) {
        As[lk + 0][lr] = av.x; As[lk + 1][lr] = av.y;
        As[lk + 2][lr] = av.z; As[lk + 3][lr] = av.w;
        Bs[lk + 0][lr] = bv.x; Bs[lk + 1][lr] = bv.y;
        Bs[lk + 2][lr] = bv.z; Bs[lk + 3][lr] = bv.w;
        __syncthreads();

        if (kt + BK < kchunk) {
            av = *(const float4*)(ap + kt + BK);
            bv = *(const float4*)(bp + kt + BK);
        }

        #pragma unroll
        for (int kk = 0; kk < BK; kk++) {
            float4 a0 = *(const float4*)&As[kk][ty * 8];
            float4 a1 = *(const float4*)&As[kk][ty * 8 + 4];
            float4 b0 = *(const float4*)&Bs[kk][tx * 8];
            float4 b1 = *(const float4*)&Bs[kk][tx * 8 + 4];
            float a[8] = {a0.x, a0.y, a0.z, a0.w, a1.x, a1.y, a1.z, a1.w};
            float b[8] = {b0.x, b0.y, b0.z, b0.w, b1.x, b1.y, b1.z, b1.w};
            #pragma unroll
            for (int i = 0; i < 8; i++)
                #pragma unroll
                for (int j = 0; j < 8; j++)
                    acc[i][j] = fmaf(a[i], b[j], acc[i][j]);
        }
        __syncthreads();
    }

    if (gridDim.z == 1) {
        #pragma unroll
        for (int i = 0; i < 8; i++) {
            size_t r = (size_t)(m0 + ty * 8 + i);
            #pragma unroll
            for (int j = 0; j < 8; j += 4) {
                int n = n0 + tx * 8 + j;
                float4 v;
                v.x = acc[i][j + 0] + bias[n + 0];
                v.y = acc[i][j + 1] + bias[n + 1];
                v.z = acc[i][j + 2] + bias[n + 2];
                v.w = acc[i][j + 3] + bias[n + 3];
                *(float4*)&Cdirect[r * N + n] = v;
            }
        }
    } else {
        float* pp = partial + ((size_t)s * M + m0) * N;
        #pragma unroll
        for (int i = 0; i < 8; i++) {
            size_t r = (size_t)(ty * 8 + i);
            #pragma unroll
            for (int j = 0; j < 8; j += 4) {
                int n = n0 + tx * 8 + j;
                float4 v = {acc[i][j], acc[i][j + 1], acc[i][j + 2], acc[i][j + 3]};
                *(float4*)&pp[r * N + n] = v;
            }
        }
    }
}

__global__ void reduce_splitk(const float* __restrict__ part,
                              const float* __restrict__ bias,
                              float* __restrict__ C, int MN, int N, int S)
{
    int i = blockIdx.x * 256 + threadIdx.x;
    if (i >= MN) return;
    float a = bias[i & (N - 1)];   // N is a power of two here (1024)
    for (int s = 0; s < S; s++) a += part[(size_t)s * MN + i];
    C[i] = a;
}

// ---------------- encoder scan: 32 CTAs x 512 thr, W_hh register-resident ----------------
__global__ void __launch_bounds__(512, 1) enc_scan_kernel(
    const float* __restrict__ Whh, const float* __restrict__ bhh)
{
    __shared__ float sh[NH];
    const int c     = blockIdx.x;
    const int tid   = threadIdx.x;
    const int row   = c * 32 + (tid >> 4);
    const int chunk = tid & 15;

    // permuted preload of W row-slice: reg i matches sh[chunk*64 + ((i+chunk)&15)*4]
    float w[64];
    {
        const float* wp = Whh + (size_t)row * NH + chunk * 64;
        #pragma unroll
        for (int i = 0; i < 16; i++) {
            int off = ((i + chunk) & 15) * 4;
            w[4 * i + 0] = wp[off + 0]; w[4 * i + 1] = wp[off + 1];
            w[4 * i + 2] = wp[off + 2]; w[4 * i + 3] = wp[off + 3];
        }
    }
    const float bias = bhh[row];

    unsigned target = 0;
    for (int t = 0; t < ENC; t++) {
        const float* hp = t ? (g_enc_out + (size_t)(t - 1) * NH) : g_h0;
        if (tid < 256) *(float4*)&sh[tid * 4] = __ldcg((const float4*)hp + tid);
        float xwv = (chunk == 0) ? g_xw_enc[(size_t)t * NH + row] : 0.f;
        __syncthreads();

        const float* shp = &sh[chunk * 64];
        float acc = 0.f;
        #pragma unroll
        for (int i = 0; i < 16; i++) {
            float4 hv = *(const float4*)&shp[((i + chunk) & 15) * 4];
            acc = fmaf(w[4 * i + 0], hv.x, acc);
            acc = fmaf(w[4 * i + 1], hv.y, acc);
            acc = fmaf(w[4 * i + 2], hv.z, acc);
            acc = fmaf(w[4 * i + 3], hv.w, acc);
        }
        #pragma unroll
        for (int o = 8; o > 0; o >>= 1) acc += __shfl_xor_sync(0xffffffffu, acc, o);

        if (chunk == 0)
            g_enc_out[(size_t)t * NH + row] = tanh_fast(acc + xwv + bias);
        __syncthreads();
        target += 32;
        grid_bar(&g_bar_enc, target, tid);
    }
}

// ---------------- decoder scan ----------------
struct DecSmem {
    float sA[16 * NH];        // this CTA's 16 rows of A
    float sE[ENC * 32];       // enc_out column slice [512][32]
    float sh[NH];
    float sw[ENC];
    float cred[16][33];
    float red[32];
    float bc[2];
};

extern __shared__ unsigned char dec_dyn[];

__global__ void __launch_bounds__(512, 1) dec_scan_kernel(
    const float* __restrict__ Whh, const float* __restrict__ bhh,
    const float* __restrict__ A, float* __restrict__ attns)
{
    DecSmem& S = *reinterpret_cast<DecSmem*>(dec_dyn);
    const int c     = blockIdx.x;
    const int tid   = threadIdx.x;
    const int row   = c * 32 + (tid >> 4);
    const int chunk = tid & 15;
    const int warp  = tid >> 5;
    const int lane  = tid & 31;

    float w[64];
    {
        const float* wp = Whh + (size_t)row * NH + chunk * 64;
        #pragma unroll
        for (int i = 0; i < 16; i++) {
            int off = ((i + chunk) & 15) * 4;
            w[4 * i + 0] = wp[off + 0]; w[4 * i + 1] = wp[off + 1];
            w[4 * i + 2] = wp[off + 2]; w[4 * i + 3] = wp[off + 3];
        }
    }
    const float bias = bhh[row];

    // one-time stage: A rows [16c,16c+16), enc_out cols [32c,32c+32)
    for (int idx = tid; idx < 16 * NH; idx += 512)
        S.sA[idx] = A[((size_t)c * 16 + (idx >> 10)) * NH + (idx & (NH - 1))];
    for (int idx = tid; idx < ENC * 32; idx += 512)
        S.sE[idx] = g_enc_out[(size_t)(idx >> 5) * NH + c * 32 + (idx & 31)];
    __syncthreads();

    unsigned target = 0;
    for (int t = 0; t < DEC; t++) {
        // ---- phase 1: h_new ----
        const float* hp = t ? (g_hcat + (size_t)(t - 1) * 2 * NH)
                            : (g_enc_out + (size_t)(ENC - 1) * NH);
        if (tid < 256) *(float4*)&S.sh[tid * 4] = __ldcg((const float4*)hp + tid);
        float xwv = (chunk == 0) ? g_xw_dec[(size_t)t * NH + row] : 0.f;
        __syncthreads();

        const float* shp = &S.sh[chunk * 64];
        float acc = 0.f;
        #pragma unroll
        for (int i = 0; i < 16; i++) {
            float4 hv = *(const float4*)&shp[((i + chunk) & 15) * 4];
            acc = fmaf(w[4 * i + 0], hv.x, acc);
            acc = fmaf(w[4 * i + 1], hv.y, acc);
            acc = fmaf(w[4 * i + 2], hv.z, acc);
            acc = fmaf(w[4 * i + 3], hv.w, acc);
        }
        #pragma unroll
        for (int o = 8; o > 0; o >>= 1) acc += __shfl_xor_sync(0xffffffffu, acc, o);
        if (chunk == 0)
            g_hcat[(size_t)t * 2 * NH + row] = tanh_fast(acc + xwv + bias);
        __syncthreads();
        target += 32;
        grid_bar(&g_bar_dec, target, tid);

        // ---- phase 2: scores = A @ h (16 per CTA, one warp each) ----
        if (tid < 256)
            *(float4*)&S.sh[tid * 4] = __ldcg((const float4*)(g_hcat + (size_t)t * 2 * NH) + tid);
        __syncthreads();
        {
            const float* ar = &S.sA[warp * NH];
            float sacc = 0.f;
            #pragma unroll
            for (int i = 0; i < 32; i++)
                sacc = fmaf(ar[lane + 32 * i], S.sh[lane + 32 * i], sacc);
            #pragma unroll
            for (int o = 16; o > 0; o >>= 1) sacc += __shfl_xor_sync(0xffffffffu, sacc, o);
            if (lane == 0) g_scores[c * 16 + warp] = sacc;
        }
        __syncthreads();
        target += 32;
        grid_bar(&g_bar_dec, target, tid);

        // ---- phase 3: softmax + context ----
        float sc = __ldcg(&g_scores[tid]);
        float mx = sc;
        #pragma unroll
        for (int o = 16; o > 0; o >>= 1) mx = fmaxf(mx, __shfl_xor_sync(0xffffffffu, mx, o));
        if (lane == 0) S.red[warp] = mx;
        __syncthreads();
        if (tid < 16) {
            float v = S.red[tid];
            #pragma unroll
            for (int o = 8; o > 0; o >>= 1) v = fmaxf(v, __shfl_xor_sync(0xffffu, v, o));
            if (tid == 0) S.bc[0] = v;
        }
        __syncthreads();
        float e = __expf(sc - S.bc[0]);
        float sm = e;
        #pragma unroll
        for (int o = 16; o > 0; o >>= 1) sm += __shfl_xor_sync(0xffffffffu, sm, o);
        if (lane == 0) S.red[warp] = sm;
        __syncthreads();
        if (tid < 16) {
            float v = S.red[tid];
            #pragma unroll
            for (int o = 8; o > 0; o >>= 1) v += __shfl_xor_sync(0xffffu, v, o);
            if (tid == 0) S.bc[1] = v;
        }
        __syncthreads();
        float wgt = e / S.bc[1];
        S.sw[tid] = wgt;
        if (c == 0) attns[(size_t)t * ENC + tid] = wgt;
        __syncthreads();

        // context cols [32c,32c+32): warp g covers enc rows [32g,32g+32)
        {
            float ca = 0.f;
            const float* ep = &S.sE[warp * 32 * 32];
            #pragma unroll
            for (int ii = 0; ii < 32; ii++)
                ca = fmaf(S.sw[warp * 32 + ii], ep[ii * 32 + lane], ca);
            S.cred[warp][lane] = ca;
            __syncthreads();
            if (tid < 32) {
                float cs = 0.f;
                #pragma unroll
                for (int g2 = 0; g2 < 16; g2++) cs += S.cred[g2][tid];
                g_hcat[(size_t)t * 2 * NH + NH + c * 32 + tid] = cs;
            }
        }
        // next iteration's leading __syncthreads orders remaining smem reuse
    }
}

// ---------------- launch ----------------
extern "C" void kernel_launch(void* const* d_in, const int* in_sizes, int n_in,
                              void* d_out, int out_size)
{
    const float* enc_input = (const float*)d_in[0];
    const float* hidden    = (const float*)d_in[1];
    const float* dec_input = (const float*)d_in[2];
    const float* enc_W_ih  = (const float*)d_in[3];
    const float* enc_W_hh  = (const float*)d_in[4];
    const float* enc_b_ih  = (const float*)d_in[5];
    const float* enc_b_hh  = (const float*)d_in[6];
    const float* dec_W_ih  = (const float*)d_in[7];
    const float* dec_W_hh  = (const float*)d_in[8];
    const float* dec_b_ih  = (const float*)d_in[9];
    const float* dec_b_hh  = (const float*)d_in[10];
    const float* attn_W    = (const float*)d_in[11];
    const float* attn_b    = (const float*)d_in[12];
    const float* out_W     = (const float*)d_in[13];
    const float* out_b     = (const float*)d_in[14];

    float* out   = (float*)d_out;
    float* outs  = out;                              // [256, 32000]
    float* attns = out + (size_t)DEC * N_CLASS;      // [256, 512]

    float *p_xw_enc, *p_enc_out, *p_A, *p_xw_dec, *p_hcat, *p_part;
    cudaGetSymbolAddress((void**)&p_xw_enc, g_xw_enc);
    cudaGetSymbolAddress((void**)&p_enc_out, g_enc_out);
    cudaGetSymbolAddress((void**)&p_A, g_A);
    cudaGetSymbolAddress((void**)&p_xw_dec, g_xw_dec);
    cudaGetSymbolAddress((void**)&p_hcat, g_hcat);
    cudaGetSymbolAddress((void**)&p_part, g_part);

    cudaFuncSetAttribute(dec_scan_kernel,
                         cudaFuncAttributeMaxDynamicSharedMemorySize, (int)sizeof(DecSmem));

    init_kernel<<<4, 256>>>(hidden);

    // enc_xw = enc_input @ enc_W_ih^T + b : M=512,N=1024,K=32000, split 8
    gemm_splitk<<<dim3(NH / BN, ENC / BM, 8), 256>>>(
        enc_input, enc_W_ih, nullptr, nullptr, p_part, ENC, NH, N_CLASS, N_CLASS / 8);
    reduce_splitk<<<(ENC * NH) / 256, 256>>>(p_part, enc_b_ih, p_xw_enc, ENC * NH, NH, 8);

    // dec_xw = dec_input @ dec_W_ih^T + b : M=256,N=1024,K=32000, split 16
    gemm_splitk<<<dim3(NH / BN, DEC / BM, 16), 256>>>(
        dec_input, dec_W_ih, nullptr, nullptr, p_part, DEC, NH, N_CLASS, N_CLASS / 16);
    reduce_splitk<<<(DEC * NH) / 256, 256>>>(p_part, dec_b_ih, p_xw_dec, DEC * NH, NH, 16);

    // encoder scan
    enc_scan_kernel<<<32, 512>>>(enc_W_hh, enc_b_hh);

    // A = enc_out @ attn_W^T + b : M=512,N=1024,K=1024, split 4
    gemm_splitk<<<dim3(NH / BN, ENC / BM, 4), 256>>>(
        p_enc_out, attn_W, nullptr, nullptr, p_part, ENC, NH, NH, NH / 4);
    reduce_splitk<<<(ENC * NH) / 256, 256>>>(p_part, attn_b, p_A, ENC * NH, NH, 4);

    // decoder scan
    dec_scan_kernel<<<32, 512, sizeof(DecSmem)>>>(dec_W_hh, dec_b_hh, p_A, attns);

    // outs = hcat @ out_W^T + out_b : M=256,N=32000,K=2048, no split (direct+bias)
    gemm_splitk<<<dim3(N_CLASS / BN, DEC / BM, 1), 256>>>(
        p_hcat, out_W, out_b, outs, nullptr, DEC, N_CLASS, 2 * NH, 2 * NH);
}

// round 8
// speedup vs baseline: 2.5851x; 1.3026x over previous
#include <cuda_runtime.h>
#include <cuda_bf16.h>
#include <math.h>
#include <stdint.h>

#define N_CLASS 32000
#define NH      1024
#define ENC     512
#define DEC     256

// ---------------- scratch (no allocations allowed) ----------------
__device__ float g_xw_enc[ENC * NH];
__device__ float g_enc_out[ENC * NH];
__device__ float g_A[ENC * NH];
__device__ float g_xw_dec[DEC * NH];
__device__ float g_hcat[DEC * 2 * NH];
__device__ float g_scores[ENC];
__device__ float g_h0[NH];
__device__ float g_part[8 * 512 * 1024];       // split-K partials (16MB)
__device__ unsigned g_flags_enc[32 * 32];      // one 128B line per CTA
__device__ unsigned g_flags_dec[32 * 32];

__global__ void init_kernel(const float* __restrict__ hidden) {
    int i = blockIdx.x * blockDim.x + threadIdx.x;
    if (i < 1024) { g_flags_enc[i] = 0u; g_flags_dec[i] = 0u; }
    if (i < NH) g_h0[i] = hidden[i];
}

// ---------------- small helpers ----------------
__device__ __forceinline__ float tanh_fast(float x) {
    float e = __expf(2.f * x);
    return 1.f - 2.f / (e + 1.f);
}

__device__ __forceinline__ unsigned su32(const void* p) {
    return (unsigned)__cvta_generic_to_shared(p);
}

// flag-array grid barrier: CTA c publishes val on its own line; all poll 32 lines.
__device__ __forceinline__ void gbar(unsigned* flags, unsigned val, int tid, int cta) {
    __syncthreads();
    if (tid < 32) {
        if (tid == 0)
            asm volatile("st.release.gpu.global.u32 [%0], %1;"
                         :: "l"(flags + (size_t)cta * 32), "r"(val) : "memory");
        unsigned v;
        do {
            asm volatile("ld.acquire.gpu.global.u32 %0, [%1];"
                         : "=r"(v) : "l"(flags + (size_t)tid * 32) : "memory");
        } while (__any_sync(0xffffffffu, v < val));
    }
    __syncthreads();
}

// ---------------- warp-MMA primitives (generic PTX, lowers to HMMA) ----------------
__device__ __forceinline__ void ldm_x4(unsigned* r, unsigned addr) {
    asm volatile("ldmatrix.sync.aligned.m8n8.x4.shared.b16 {%0,%1,%2,%3}, [%4];"
                 : "=r"(r[0]), "=r"(r[1]), "=r"(r[2]), "=r"(r[3]) : "r"(addr));
}
__device__ __forceinline__ void ldm_x2(unsigned* r, unsigned addr) {
    asm volatile("ldmatrix.sync.aligned.m8n8.x2.shared.b16 {%0,%1}, [%2];"
                 : "=r"(r[0]), "=r"(r[1]) : "r"(addr));
}
__device__ __forceinline__ void mma_bf16(float* d, const unsigned* a, const unsigned* b) {
    asm volatile("mma.sync.aligned.m16n8k16.row.col.f32.bf16.bf16.f32 "
                 "{%0,%1,%2,%3}, {%4,%5,%6,%7}, {%8,%9}, {%0,%1,%2,%3};"
                 : "+f"(d[0]), "+f"(d[1]), "+f"(d[2]), "+f"(d[3])
                 : "r"(a[0]), "r"(a[1]), "r"(a[2]), "r"(a[3]), "r"(b[0]), "r"(b[1]));
}

// ---------------- bf16-split tensor GEMM ----------------
// C[M,N] = A[M,K] @ B[N,K]^T (+bias). 128x128 tile, BK=64, alternating buffers.
// smem per stage: A_hi | A_lo | B_hi | B_lo, each 128 rows x 72 halves (pad 8).
#define BK        64
#define PADH      72
#define TILE_B    (128 * PADH * 2)       // 18432
#define STAGE_B   (4 * TILE_B)           // 73728
#define GEMM_SMEM (2 * STAGE_B)          // 147456

__device__ __forceinline__ void load_tile_split(
    const float* __restrict__ src, int K, int row0, long col0,
    unsigned dst_hi, unsigned dst_lo, int tid)
{
    // tile = 128 rows x 64 fp32: 2048 float4 = 256 thr x 8 iters
    #pragma unroll
    for (int i = 0; i < 8; i++) {
        int j = tid + 256 * i;
        int r = j >> 4, c = j & 15;
        float4 v = *(const float4*)(src + (size_t)(row0 + r) * K + col0 + c * 4);
        __nv_bfloat162 h0 = __floats2bfloat162_rn(v.x, v.y);
        __nv_bfloat162 h1 = __floats2bfloat162_rn(v.z, v.w);
        float lx = v.x - __bfloat162float(h0.x);
        float ly = v.y - __bfloat162float(h0.y);
        float lz = v.z - __bfloat162float(h1.x);
        float lw = v.w - __bfloat162float(h1.y);
        __nv_bfloat162 l0 = __floats2bfloat162_rn(lx, ly);
        __nv_bfloat162 l1 = __floats2bfloat162_rn(lz, lw);
        unsigned boff = (unsigned)(r * PADH + c * 4) * 2;
        unsigned long long hv = ((unsigned long long)(*(unsigned*)&h1) << 32) | (*(unsigned*)&h0);
        unsigned long long lv = ((unsigned long long)(*(unsigned*)&l1) << 32) | (*(unsigned*)&l0);
        asm volatile("st.shared.b64 [%0], %1;" :: "r"(dst_hi + boff), "l"(hv) : "memory");
        asm volatile("st.shared.b64 [%0], %1;" :: "r"(dst_lo + boff), "l"(lv) : "memory");
    }
}

extern __shared__ unsigned char gemm_dyn[];

__global__ void __launch_bounds__(256, 1) gemm_mma(
    const float* __restrict__ Am, const float* __restrict__ Bm,
    const float* __restrict__ bias, float* __restrict__ Cdirect,
    float* __restrict__ partial,
    int M, int N, int K, int kt_per_split, int kt_total)
{
    const unsigned sbase = su32(gemm_dyn);
    const int tid  = threadIdx.x;
    const int wid  = tid >> 5;
    const int lane = tid & 31;
    const int n0 = blockIdx.x * 128;
    const int m0 = blockIdx.y * 128;
    const int s  = blockIdx.z;
    const long kt0 = (long)s * kt_per_split;
    int nt_ = kt_total - (int)kt0;
    if (nt_ > kt_per_split) nt_ = kt_per_split;
    const int ntiles = nt_;

    const int wr = wid >> 2;     // 0..1 (64-row group)
    const int wc = wid & 3;      // 0..3 (32-col group)

    float acc[4][4][4];
    #pragma unroll
    for (int mt = 0; mt < 4; mt++)
        #pragma unroll
        for (int nt = 0; nt < 4; nt++)
            #pragma unroll
            for (int q = 0; q < 4; q++) acc[mt][nt][q] = 0.f;

    // per-warp ldmatrix source addresses (constant parts)
    const int arow = wr * 64 + (lane & 15);
    const int acolh = (lane >> 4) * 8;            // 0 or 8
    const int brow = wc * 32 + (lane & 7);
    const int bcolh = ((lane >> 3) & 1) * 8;      // 0 or 8 (lanes 16-31 mirror 0-15)

    for (int kt = 0; kt < ntiles; kt++) {
        const unsigned bb = sbase + (unsigned)(kt & 1) * STAGE_B;
        const unsigned Ah = bb, Al = bb + TILE_B, Bh = bb + 2 * TILE_B, Bl = bb + 3 * TILE_B;

        long col0 = (kt0 + kt) * BK;
        load_tile_split(Am, K, m0, col0, Ah, Al, tid);
        load_tile_split(Bm, K, n0, col0, Bh, Bl, tid);
        __syncthreads();

        #pragma unroll
        for (int kk = 0; kk < 4; kk++) {
            unsigned a_hi[4][4], a_lo[4][4], b_hi[4][2], b_lo[4][2];
            #pragma unroll
            for (int mt = 0; mt < 4; mt++) {
                unsigned off = (unsigned)((arow + mt * 16) * PADH + kk * 16 + acolh) * 2;
                ldm_x4(a_hi[mt], Ah + off);
                ldm_x4(a_lo[mt], Al + off);
            }
            #pragma unroll
            for (int nt = 0; nt < 4; nt++) {
                unsigned off = (unsigned)((brow + nt * 8) * PADH + kk * 16 + bcolh) * 2;
                ldm_x2(b_hi[nt], Bh + off);
                ldm_x2(b_lo[nt], Bl + off);
            }
            #pragma unroll
            for (int mt = 0; mt < 4; mt++)
                #pragma unroll
                for (int nt = 0; nt < 4; nt++) {
                    mma_bf16(acc[mt][nt], a_hi[mt], b_hi[nt]);
                    mma_bf16(acc[mt][nt], a_hi[mt], b_lo[nt]);
                    mma_bf16(acc[mt][nt], a_lo[mt], b_hi[nt]);
                }
        }
        __syncthreads();
    }

    // epilogue: thread (g=lane>>2, tig=lane&3) owns rows g, g+8 and cols tig*2, tig*2+1
    const int g   = lane >> 2;
    const int tig = lane & 3;
    if (gridDim.z == 1) {
        #pragma unroll
        for (int mt = 0; mt < 4; mt++) {
            int row = m0 + wr * 64 + mt * 16 + g;
            #pragma unroll
            for (int nt = 0; nt < 4; nt++) {
                int col = n0 + wc * 32 + nt * 8 + tig * 2;
                float b0 = bias[col], b1 = bias[col + 1];
                float2 v0 = {acc[mt][nt][0] + b0, acc[mt][nt][1] + b1};
                float2 v1 = {acc[mt][nt][2] + b0, acc[mt][nt][3] + b1};
                *(float2*)&Cdirect[(size_t)row * N + col] = v0;
                *(float2*)&Cdirect[(size_t)(row + 8) * N + col] = v1;
            }
        }
    } else {
        #pragma unroll
        for (int mt = 0; mt < 4; mt++) {
            int row = m0 + wr * 64 + mt * 16 + g;   // FIX: include m0 tile offset
            float* pp = partial + ((size_t)s * M + row) * N;
            #pragma unroll
            for (int nt = 0; nt < 4; nt++) {
                int col = n0 + wc * 32 + nt * 8 + tig * 2;
                float2 v0 = {acc[mt][nt][0], acc[mt][nt][1]};
                float2 v1 = {acc[mt][nt][2], acc[mt][nt][3]};
                *(float2*)&pp[col] = v0;
                *(float2*)&pp[(size_t)8 * N + col] = v1;
            }
        }
    }
}

__global__ void reduce_splitk(const float* __restrict__ part,
                              const float* __restrict__ bias,
                              float* __restrict__ C, int MN, int N, int S)
{
    int i = blockIdx.x * 256 + threadIdx.x;
    if (i >= MN) return;
    float a = bias[i & (N - 1)];   // N = 1024 (power of two)
    for (int s = 0; s < S; s++) a += part[(size_t)s * MN + i];
    C[i] = a;
}

// ---------------- encoder scan: 32 CTAs x 512 thr, W_hh register-resident ----------------
__global__ void __launch_bounds__(512, 1) enc_scan_kernel(
    const float* __restrict__ Whh, const float* __restrict__ bhh)
{
    __shared__ float sh[NH];
    const int c     = blockIdx.x;
    const int tid   = threadIdx.x;
    const int row   = c * 32 + (tid >> 4);
    const int chunk = tid & 15;

    float w[64];
    {
        const float* wp = Whh + (size_t)row * NH + chunk * 64;
        #pragma unroll
        for (int i = 0; i < 16; i++) {
            int off = ((i + chunk) & 15) * 4;
            w[4*i+0] = wp[off+0]; w[4*i+1] = wp[off+1];
            w[4*i+2] = wp[off+2]; w[4*i+3] = wp[off+3];
        }
    }
    const float bias = bhh[row];

    for (int t = 0; t < ENC; t++) {
        const float* hp = t ? (g_enc_out + (size_t)(t - 1) * NH) : g_h0;
        if (tid < 256) *(float4*)&sh[tid * 4] = __ldcg((const float4*)hp + tid);
        float xwv = (chunk == 0) ? g_xw_enc[(size_t)t * NH + row] : 0.f;
        __syncthreads();

        const float* shp = &sh[chunk * 64];
        float acc = 0.f;
        #pragma unroll
        for (int i = 0; i < 16; i++) {
            float4 hv = *(const float4*)&shp[((i + chunk) & 15) * 4];
            acc = fmaf(w[4*i+0], hv.x, acc);
            acc = fmaf(w[4*i+1], hv.y, acc);
            acc = fmaf(w[4*i+2], hv.z, acc);
            acc = fmaf(w[4*i+3], hv.w, acc);
        }
        #pragma unroll
        for (int o = 8; o > 0; o >>= 1) acc += __shfl_xor_sync(0xffffffffu, acc, o);

        if (chunk == 0)
            g_enc_out[(size_t)t * NH + row] = tanh_fast(acc + xwv + bias);
        gbar(g_flags_enc, (unsigned)(t + 1), tid, c);
    }
}

// ---------------- decoder scan ----------------
struct DecSmem {
    float sA[16 * NH];
    float sE[ENC * 32];
    float sh[NH];
    float sw[ENC];
    float cred[16][33];
    float red[32];
    float bc[2];
};

extern __shared__ unsigned char dec_dyn[];

__global__ void __launch_bounds__(512, 1) dec_scan_kernel(
    const float* __restrict__ Whh, const float* __restrict__ bhh,
    const float* __restrict__ A, float* __restrict__ attns)
{
    DecSmem& S = *reinterpret_cast<DecSmem*>(dec_dyn);
    const int c     = blockIdx.x;
    const int tid   = threadIdx.x;
    const int row   = c * 32 + (tid >> 4);
    const int chunk = tid & 15;
    const int warp  = tid >> 5;
    const int lane  = tid & 31;

    float w[64];
    {
        const float* wp = Whh + (size_t)row * NH + chunk * 64;
        #pragma unroll
        for (int i = 0; i < 16; i++) {
            int off = ((i + chunk) & 15) * 4;
            w[4*i+0] = wp[off+0]; w[4*i+1] = wp[off+1];
            w[4*i+2] = wp[off+2]; w[4*i+3] = wp[off+3];
        }
    }
    const float bias = bhh[row];

    for (int idx = tid; idx < 16 * NH; idx += 512)
        S.sA[idx] = A[((size_t)c * 16 + (idx >> 10)) * NH + (idx & (NH - 1))];
    for (int idx = tid; idx < ENC * 32; idx += 512)
        S.sE[idx] = g_enc_out[(size_t)(idx >> 5) * NH + c * 32 + (idx & 31)];
    __syncthreads();

    for (int t = 0; t < DEC; t++) {
        // phase 1: h_new
        const float* hp = t ? (g_hcat + (size_t)(t - 1) * 2 * NH)
                            : (g_enc_out + (size_t)(ENC - 1) * NH);
        if (tid < 256) *(float4*)&S.sh[tid * 4] = __ldcg((const float4*)hp + tid);
        float xwv = (chunk == 0) ? g_xw_dec[(size_t)t * NH + row] : 0.f;
        __syncthreads();

        const float* shp = &S.sh[chunk * 64];
        float acc = 0.f;
        #pragma unroll
        for (int i = 0; i < 16; i++) {
            float4 hv = *(const float4*)&shp[((i + chunk) & 15) * 4];
            acc = fmaf(w[4*i+0], hv.x, acc);
            acc = fmaf(w[4*i+1], hv.y, acc);
            acc = fmaf(w[4*i+2], hv.z, acc);
            acc = fmaf(w[4*i+3], hv.w, acc);
        }
        #pragma unroll
        for (int o = 8; o > 0; o >>= 1) acc += __shfl_xor_sync(0xffffffffu, acc, o);
        if (chunk == 0)
            g_hcat[(size_t)t * 2 * NH + row] = tanh_fast(acc + xwv + bias);
        gbar(g_flags_dec, (unsigned)(2 * t + 1), tid, c);

        // phase 2: scores = A @ h (16 per CTA, one warp each)
        if (tid < 256)
            *(float4*)&S.sh[tid * 4] = __ldcg((const float4*)(g_hcat + (size_t)t * 2 * NH) + tid);
        __syncthreads();
        {
            const float* ar = &S.sA[warp * NH];
            float sacc = 0.f;
            #pragma unroll
            for (int i = 0; i < 32; i++)
                sacc = fmaf(ar[lane + 32 * i], S.sh[lane + 32 * i], sacc);
            #pragma unroll
            for (int o = 16; o > 0; o >>= 1) sacc += __shfl_xor_sync(0xffffffffu, sacc, o);
            if (lane == 0) g_scores[c * 16 + warp] = sacc;
        }
        gbar(g_flags_dec, (unsigned)(2 * t + 2), tid, c);

        // phase 3: softmax + context
        float sc = __ldcg(&g_scores[tid]);
        float mx = sc;
        #pragma unroll
        for (int o = 16; o > 0; o >>= 1) mx = fmaxf(mx, __shfl_xor_sync(0xffffffffu, mx, o));
        if (lane == 0) S.red[warp] = mx;
        __syncthreads();
        if (tid < 16) {
            float v = S.red[tid];
            #pragma unroll
            for (int o = 8; o > 0; o >>= 1) v = fmaxf(v, __shfl_xor_sync(0xffffu, v, o));
            if (tid == 0) S.bc[0] = v;
        }
        __syncthreads();
        float e = __expf(sc - S.bc[0]);
        float sm = e;
        #pragma unroll
        for (int o = 16; o > 0; o >>= 1) sm += __shfl_xor_sync(0xffffffffu, sm, o);
        if (lane == 0) S.red[warp] = sm;
        __syncthreads();
        if (tid < 16) {
            float v = S.red[tid];
            #pragma unroll
            for (int o = 8; o > 0; o >>= 1) v += __shfl_xor_sync(0xffffu, v, o);
            if (tid == 0) S.bc[1] = v;
        }
        __syncthreads();
        float wgt = e / S.bc[1];
        S.sw[tid] = wgt;
        if (c == 0) attns[(size_t)t * ENC + tid] = wgt;
        __syncthreads();

        {
            float ca = 0.f;
            const float* ep = &S.sE[warp * 32 * 32];
            #pragma unroll
            for (int ii = 0; ii < 32; ii++)
                ca = fmaf(S.sw[warp * 32 + ii], ep[ii * 32 + lane], ca);
            S.cred[warp][lane] = ca;
            __syncthreads();
            if (tid < 32) {
                float cs = 0.f;
                #pragma unroll
                for (int g2 = 0; g2 < 16; g2++) cs += S.cred[g2][tid];
                g_hcat[(size_t)t * 2 * NH + NH + c * 32 + tid] = cs;
            }
        }
        __syncthreads();
    }
}

// ---------------- launch ----------------
extern "C" void kernel_launch(void* const* d_in, const int* in_sizes, int n_in,
                              void* d_out, int out_size)
{
    const float* enc_input = (const float*)d_in[0];
    const float* hidden    = (const float*)d_in[1];
    const float* dec_input = (const float*)d_in[2];
    const float* enc_W_ih  = (const float*)d_in[3];
    const float* enc_W_hh  = (const float*)d_in[4];
    const float* enc_b_ih  = (const float*)d_in[5];
    const float* enc_b_hh  = (const float*)d_in[6];
    const float* dec_W_ih  = (const float*)d_in[7];
    const float* dec_W_hh  = (const float*)d_in[8];
    const float* dec_b_ih  = (const float*)d_in[9];
    const float* dec_b_hh  = (const float*)d_in[10];
    const float* attn_W    = (const float*)d_in[11];
    const float* attn_b    = (const float*)d_in[12];
    const float* out_W     = (const float*)d_in[13];
    const float* out_b     = (const float*)d_in[14];

    float* out   = (float*)d_out;
    float* outs  = out;                              // [256, 32000]
    float* attns = out + (size_t)DEC * N_CLASS;      // [256, 512]

    float *p_xw_enc, *p_enc_out, *p_A, *p_xw_dec, *p_hcat, *p_part;
    cudaGetSymbolAddress((void**)&p_xw_enc, g_xw_enc);
    cudaGetSymbolAddress((void**)&p_enc_out, g_enc_out);
    cudaGetSymbolAddress((void**)&p_A, g_A);
    cudaGetSymbolAddress((void**)&p_xw_dec, g_xw_dec);
    cudaGetSymbolAddress((void**)&p_hcat, g_hcat);
    cudaGetSymbolAddress((void**)&p_part, g_part);

    cudaFuncSetAttribute(gemm_mma,
                         cudaFuncAttributeMaxDynamicSharedMemorySize, GEMM_SMEM);
    cudaFuncSetAttribute(dec_scan_kernel,
                         cudaFuncAttributeMaxDynamicSharedMemorySize, (int)sizeof(DecSmem));

    init_kernel<<<4, 256>>>(hidden);

    // enc_xw = enc_input @ enc_W_ih^T + b : M=512,N=1024,K=32000, split 4 (125 kt each)
    gemm_mma<<<dim3(8, 4, 4), 256, GEMM_SMEM>>>(
        enc_input, enc_W_ih, nullptr, nullptr, p_part, ENC, NH, N_CLASS, 125, 500);
    reduce_splitk<<<(ENC * NH) / 256, 256>>>(p_part, enc_b_ih, p_xw_enc, ENC * NH, NH, 4);

    // dec_xw = dec_input @ dec_W_ih^T + b : M=256,N=1024,K=32000, split 8 (63/59 kt)
    gemm_mma<<<dim3(8, 2, 8), 256, GEMM_SMEM>>>(
        dec_input, dec_W_ih, nullptr, nullptr, p_part, DEC, NH, N_CLASS, 63, 500);
    reduce_splitk<<<(DEC * NH) / 256, 256>>>(p_part, dec_b_ih, p_xw_dec, DEC * NH, NH, 8);

    // encoder scan
    enc_scan_kernel<<<32, 512>>>(enc_W_hh, enc_b_hh);

    // A = enc_out @ attn_W^T + b : M=512,N=1024,K=1024, direct
    gemm_mma<<<dim3(8, 4, 1), 256, GEMM_SMEM>>>(
        p_enc_out, attn_W, attn_b, p_A, nullptr, ENC, NH, NH, 16, 16);

    // decoder scan
    dec_scan_kernel<<<32, 512, sizeof(DecSmem)>>>(dec_W_hh, dec_b_hh, p_A, attns);

    // outs = hcat @ out_W^T + out_b : M=256,N=32000,K=2048, direct
    gemm_mma<<<dim3(250, 2, 1), 256, GEMM_SMEM>>>(
        p_hcat, out_W, out_b, outs, nullptr, DEC, N_CLASS, 2 * NH, 32, 32);
}

// round 11
// speedup vs baseline: 2.8884x; 1.1173x over previous
#include <cuda_runtime.h>
#include <cuda_bf16.h>
#include <math.h>
#include <stdint.h>

#define N_CLASS 32000
#define NH      1024
#define ENC     512
#define DEC     256

// ---------------- scratch (no allocations allowed) ----------------
__device__ float g_xw_enc[ENC * NH];
__device__ float g_enc_out[ENC * NH];
__device__ float g_A[ENC * NH];
__device__ float g_xw_dec[DEC * NH];
__device__ float g_hcat[DEC * 2 * NH];
__device__ float g_h0[NH];
__device__ float g_part[8 * 512 * 1024];               // split-K partials (16MB)
__device__ unsigned long long g_hbuf_enc[2][NH];       // {tag<<32 | value} packets
__device__ unsigned long long g_hbuf_dec[2][NH];
__device__ unsigned long long g_sbuf[2][ENC];

// zero tag buffers EVERY launch (graph replays would reuse stale tags)
__global__ void init_kernel(const float* __restrict__ hidden) {
    int i = blockIdx.x * blockDim.x + threadIdx.x;
    if (i < NH) g_h0[i] = hidden[i];
    if (i < 2 * NH) {
        (&g_hbuf_enc[0][0])[i] = 0ULL;
        (&g_hbuf_dec[0][0])[i] = 0ULL;
    }
    if (i < 2 * ENC) (&g_sbuf[0][0])[i] = 0ULL;
}

// ---------------- small helpers ----------------
__device__ __forceinline__ float tanh_fast(float x) {
    float e = __expf(2.f * x);
    return 1.f - 2.f / (e + 1.f);
}
__device__ __forceinline__ unsigned su32(const void* p) {
    return (unsigned)__cvta_generic_to_shared(p);
}
// tagged publish/poll: scalar ALIGNED b64 packet {tag(hi), value(lo)}.
// Scalar 8B relaxed atomics are single-copy atomic (v2.b32 is NOT -> R9/R10 tearing).
__device__ __forceinline__ void pub_tag(unsigned long long* p, float v, int tag) {
    unsigned long long pkt = ((unsigned long long)(unsigned)tag << 32)
                           | (unsigned long long)__float_as_uint(v);
    asm volatile("st.relaxed.gpu.global.b64 [%0], %1;" :: "l"(p), "l"(pkt) : "memory");
}
__device__ __forceinline__ float poll_tag(const unsigned long long* p, int tag) {
    unsigned long long pkt;
    do {
        asm volatile("ld.relaxed.gpu.global.b64 %0, [%1];" : "=l"(pkt) : "l"(p) : "memory");
    } while ((unsigned)(pkt >> 32) != (unsigned)tag);
    return __uint_as_float((unsigned)pkt);
}

// ---------------- warp-MMA primitives (generic PTX -> HMMA) ----------------
__device__ __forceinline__ void ldm_x4(unsigned* r, unsigned addr) {
    asm volatile("ldmatrix.sync.aligned.m8n8.x4.shared.b16 {%0,%1,%2,%3}, [%4];"
                 : "=r"(r[0]), "=r"(r[1]), "=r"(r[2]), "=r"(r[3]) : "r"(addr));
}
__device__ __forceinline__ void ldm_x2(unsigned* r, unsigned addr) {
    asm volatile("ldmatrix.sync.aligned.m8n8.x2.shared.b16 {%0,%1}, [%2];"
                 : "=r"(r[0]), "=r"(r[1]) : "r"(addr));
}
__device__ __forceinline__ void mma_bf16(float* d, const unsigned* a, const unsigned* b) {
    asm volatile("mma.sync.aligned.m16n8k16.row.col.f32.bf16.bf16.f32 "
                 "{%0,%1,%2,%3}, {%4,%5,%6,%7}, {%8,%9}, {%0,%1,%2,%3};"
                 : "+f"(d[0]), "+f"(d[1]), "+f"(d[2]), "+f"(d[3])
                 : "r"(a[0]), "r"(a[1]), "r"(a[2]), "r"(a[3]), "r"(b[0]), "r"(b[1]));
}

// ---------------- bf16-split tensor GEMM, software-pipelined ----------------
#define BK        64
#define PADH      72
#define TILE_B    (128 * PADH * 2)       // 18432
#define STAGE_B   (4 * TILE_B)           // 73728
#define GEMM_SMEM (2 * STAGE_B)          // 147456

__device__ __forceinline__ void ldg_tile(
    const float* __restrict__ src, int K, int row0, long col0, int tid, float4* v)
{
    #pragma unroll
    for (int i = 0; i < 8; i++) {
        int j = tid + 256 * i;
        int r = j >> 4, c = j & 15;
        v[i] = *(const float4*)(src + (size_t)(row0 + r) * K + col0 + c * 4);
    }
}

__device__ __forceinline__ void sts_tile_split(
    const float4* v, unsigned dst_hi, unsigned dst_lo, int tid)
{
    #pragma unroll
    for (int i = 0; i < 8; i++) {
        int j = tid + 256 * i;
        int r = j >> 4, c = j & 15;
        float4 t = v[i];
        __nv_bfloat162 h0 = __floats2bfloat162_rn(t.x, t.y);
        __nv_bfloat162 h1 = __floats2bfloat162_rn(t.z, t.w);
        float lx = t.x - __bfloat162float(h0.x);
        float ly = t.y - __bfloat162float(h0.y);
        float lz = t.z - __bfloat162float(h1.x);
        float lw = t.w - __bfloat162float(h1.y);
        __nv_bfloat162 l0 = __floats2bfloat162_rn(lx, ly);
        __nv_bfloat162 l1 = __floats2bfloat162_rn(lz, lw);
        unsigned boff = (unsigned)(r * PADH + c * 4) * 2;
        unsigned long long hv = ((unsigned long long)(*(unsigned*)&h1) << 32) | (*(unsigned*)&h0);
        unsigned long long lv = ((unsigned long long)(*(unsigned*)&l1) << 32) | (*(unsigned*)&l0);
        asm volatile("st.shared.b64 [%0], %1;" :: "r"(dst_hi + boff), "l"(hv) : "memory");
        asm volatile("st.shared.b64 [%0], %1;" :: "r"(dst_lo + boff), "l"(lv) : "memory");
    }
}

extern __shared__ unsigned char gemm_dyn[];

__global__ void __launch_bounds__(256, 1) gemm_mma(
    const float* __restrict__ Am, const float* __restrict__ Bm,
    const float* __restrict__ bias, float* __restrict__ Cdirect,
    float* __restrict__ partial,
    int M, int N, int K, int kt_per_split, int kt_total)
{
    const unsigned sbase = su32(gemm_dyn);
    const int tid  = threadIdx.x;
    const int wid  = tid >> 5;
    const int lane = tid & 31;
    const int n0 = blockIdx.x * 128;
    const int m0 = blockIdx.y * 128;
    const int s  = blockIdx.z;
    const long kt0 = (long)s * kt_per_split;
    int nt_ = kt_total - (int)kt0;
    if (nt_ > kt_per_split) nt_ = kt_per_split;
    const int ntiles = nt_;

    const int wr = wid >> 2;
    const int wc = wid & 3;

    float acc[4][4][4];
    #pragma unroll
    for (int mt = 0; mt < 4; mt++)
        #pragma unroll
        for (int nt = 0; nt < 4; nt++)
            #pragma unroll
            for (int q = 0; q < 4; q++) acc[mt][nt][q] = 0.f;

    const int arow = wr * 64 + (lane & 15);
    const int acolh = (lane >> 4) * 8;
    const int brow = wc * 32 + (lane & 7);
    const int bcolh = ((lane >> 3) & 1) * 8;

    float4 va[8], vb[8];
    ldg_tile(Am, K, m0, kt0 * BK, tid, va);
    ldg_tile(Bm, K, n0, kt0 * BK, tid, vb);

    for (int kt = 0; kt < ntiles; kt++) {
        const unsigned bb = sbase + (unsigned)(kt & 1) * STAGE_B;
        const unsigned Ah = bb, Al = bb + TILE_B, Bh = bb + 2 * TILE_B, Bl = bb + 3 * TILE_B;

        sts_tile_split(va, Ah, Al, tid);
        sts_tile_split(vb, Bh, Bl, tid);
        __syncthreads();

        if (kt + 1 < ntiles) {     // overlap next-tile LDG with this tile's MMAs
            long c0 = (kt0 + kt + 1) * BK;
            ldg_tile(Am, K, m0, c0, tid, va);
            ldg_tile(Bm, K, n0, c0, tid, vb);
        }

        #pragma unroll
        for (int kk = 0; kk < 4; kk++) {
            unsigned a_hi[4][4], a_lo[4][4], b_hi[4][2], b_lo[4][2];
            #pragma unroll
            for (int mt = 0; mt < 4; mt++) {
                unsigned off = (unsigned)((arow + mt * 16) * PADH + kk * 16 + acolh) * 2;
                ldm_x4(a_hi[mt], Ah + off);
                ldm_x4(a_lo[mt], Al + off);
            }
            #pragma unroll
            for (int nt = 0; nt < 4; nt++) {
                unsigned off = (unsigned)((brow + nt * 8) * PADH + kk * 16 + bcolh) * 2;
                ldm_x2(b_hi[nt], Bh + off);
                ldm_x2(b_lo[nt], Bl + off);
            }
            #pragma unroll
            for (int mt = 0; mt < 4; mt++)
                #pragma unroll
                for (int nt = 0; nt < 4; nt++) {
                    mma_bf16(acc[mt][nt], a_hi[mt], b_hi[nt]);
                    mma_bf16(acc[mt][nt], a_hi[mt], b_lo[nt]);
                    mma_bf16(acc[mt][nt], a_lo[mt], b_hi[nt]);
                }
        }
        // alternating buffers + the single sync above give WAR safety
    }

    const int g   = lane >> 2;
    const int tig = lane & 3;
    if (gridDim.z == 1) {
        #pragma unroll
        for (int mt = 0; mt < 4; mt++) {
            int row = m0 + wr * 64 + mt * 16 + g;
            #pragma unroll
            for (int nt = 0; nt < 4; nt++) {
                int col = n0 + wc * 32 + nt * 8 + tig * 2;
                float b0 = bias[col], b1 = bias[col + 1];
                float2 v0 = {acc[mt][nt][0] + b0, acc[mt][nt][1] + b1};
                float2 v1 = {acc[mt][nt][2] + b0, acc[mt][nt][3] + b1};
                *(float2*)&Cdirect[(size_t)row * N + col] = v0;
                *(float2*)&Cdirect[(size_t)(row + 8) * N + col] = v1;
            }
        }
    } else {
        #pragma unroll
        for (int mt = 0; mt < 4; mt++) {
            int row = m0 + wr * 64 + mt * 16 + g;
            float* pp = partial + ((size_t)s * M + row) * N;
            #pragma unroll
            for (int nt = 0; nt < 4; nt++) {
                int col = n0 + wc * 32 + nt * 8 + tig * 2;
                float2 v0 = {acc[mt][nt][0], acc[mt][nt][1]};
                float2 v1 = {acc[mt][nt][2], acc[mt][nt][3]};
                *(float2*)&pp[col] = v0;
                *(float2*)&pp[(size_t)8 * N + col] = v1;
            }
        }
    }
}

__global__ void reduce_splitk(const float* __restrict__ part,
                              const float* __restrict__ bias,
                              float* __restrict__ C, int MN, int N, int S)
{
    int i = blockIdx.x * 256 + threadIdx.x;
    if (i >= MN) return;
    float a = bias[i & (N - 1)];
    for (int s = 0; s < S; s++) a += part[(size_t)s * MN + i];
    C[i] = a;
}

// ---------------- encoder scan: tagged b64 publish (tag = t+1) ----------------
__global__ void __launch_bounds__(512, 1) enc_scan_kernel(
    const float* __restrict__ Whh, const float* __restrict__ bhh)
{
    __shared__ float sh[NH];
    const int c     = blockIdx.x;
    const int tid   = threadIdx.x;
    const int row   = c * 32 + (tid >> 4);
    const int chunk = tid & 15;

    float w[64];
    {
        const float* wp = Whh + (size_t)row * NH + chunk * 64;
        #pragma unroll
        for (int i = 0; i < 16; i++) {
            int off = ((i + chunk) & 15) * 4;
            w[4*i+0] = wp[off+0]; w[4*i+1] = wp[off+1];
            w[4*i+2] = wp[off+2]; w[4*i+3] = wp[off+3];
        }
    }
    const float bias = bhh[row];

    for (int t = 0; t < ENC; t++) {
        if (t == 0) {
            if (tid < 256) *(float4*)&sh[tid * 4] = __ldcg((const float4*)g_h0 + tid);
        } else {
            const unsigned long long* src = g_hbuf_enc[(t - 1) & 1];
            sh[tid]       = poll_tag(src + tid,       t);   // step t-1 published tag t
            sh[tid + 512] = poll_tag(src + tid + 512, t);
        }
        float xwv = (chunk == 0) ? __ldcg(&g_xw_enc[(size_t)t * NH + row]) : 0.f;
        __syncthreads();

        const float* shp = &sh[chunk * 64];
        float acc = 0.f;
        #pragma unroll
        for (int i = 0; i < 16; i++) {
            float4 hv = *(const float4*)&shp[((i + chunk) & 15) * 4];
            acc = fmaf(w[4*i+0], hv.x, acc);
            acc = fmaf(w[4*i+1], hv.y, acc);
            acc = fmaf(w[4*i+2], hv.z, acc);
            acc = fmaf(w[4*i+3], hv.w, acc);
        }
        #pragma unroll
        for (int o = 8; o > 0; o >>= 1) acc += __shfl_xor_sync(0xffffffffu, acc, o);

        if (chunk == 0) {
            float h = tanh_fast(acc + xwv + bias);
            g_enc_out[(size_t)t * NH + row] = h;
            pub_tag(&g_hbuf_enc[t & 1][row], h, t + 1);
        }
        __syncthreads();   // protect sh before next step overwrites it
    }
}

// ---------------- decoder scan: tagged b64 crossings ----------------
struct DecSmem {
    float sA[16 * NH];
    float sE[ENC * 32];
    float sh[NH];
    float sw[ENC];
    float cred[16][33];
    float red[32];
    float bc[2];
};

extern __shared__ unsigned char dec_dyn[];

__global__ void __launch_bounds__(512, 1) dec_scan_kernel(
    const float* __restrict__ Whh, const float* __restrict__ bhh,
    const float* __restrict__ A, float* __restrict__ attns)
{
    DecSmem& S = *reinterpret_cast<DecSmem*>(dec_dyn);
    const int c     = blockIdx.x;
    const int tid   = threadIdx.x;
    const int row   = c * 32 + (tid >> 4);
    const int chunk = tid & 15;
    const int warp  = tid >> 5;
    const int lane  = tid & 31;

    float w[64];
    {
        const float* wp = Whh + (size_t)row * NH + chunk * 64;
        #pragma unroll
        for (int i = 0; i < 16; i++) {
            int off = ((i + chunk) & 15) * 4;
            w[4*i+0] = wp[off+0]; w[4*i+1] = wp[off+1];
            w[4*i+2] = wp[off+2]; w[4*i+3] = wp[off+3];
        }
    }
    const float bias = bhh[row];

    for (int idx = tid; idx < 16 * NH; idx += 512)
        S.sA[idx] = A[((size_t)c * 16 + (idx >> 10)) * NH + (idx & (NH - 1))];
    for (int idx = tid; idx < ENC * 32; idx += 512)
        S.sE[idx] = g_enc_out[(size_t)(idx >> 5) * NH + c * 32 + (idx & 31)];
    __syncthreads();

    for (int t = 0; t < DEC; t++) {
        // ---- phase 1: obtain h_prev, compute own rows, publish tag t+1 ----
        if (t == 0) {
            if (tid < 256)
                *(float4*)&S.sh[tid * 4] =
                    __ldcg((const float4*)(g_enc_out + (size_t)(ENC - 1) * NH) + tid);
        } else {
            const unsigned long long* src = g_hbuf_dec[(t - 1) & 1];
            S.sh[tid]       = poll_tag(src + tid,       t);
            S.sh[tid + 512] = poll_tag(src + tid + 512, t);
        }
        float xwv = (chunk == 0) ? __ldcg(&g_xw_dec[(size_t)t * NH + row]) : 0.f;
        __syncthreads();

        const float* shp = &S.sh[chunk * 64];
        float acc = 0.f;
        #pragma unroll
        for (int i = 0; i < 16; i++) {
            float4 hv = *(const float4*)&shp[((i + chunk) & 15) * 4];
            acc = fmaf(w[4*i+0], hv.x, acc);
            acc = fmaf(w[4*i+1], hv.y, acc);
            acc = fmaf(w[4*i+2], hv.z, acc);
            acc = fmaf(w[4*i+3], hv.w, acc);
        }
        #pragma unroll
        for (int o = 8; o > 0; o >>= 1) acc += __shfl_xor_sync(0xffffffffu, acc, o);
        if (chunk == 0) {
            float h = tanh_fast(acc + xwv + bias);
            g_hcat[(size_t)t * 2 * NH + row] = h;
            pub_tag(&g_hbuf_dec[t & 1][row], h, t + 1);
        }
        __syncthreads();   // all warps done reading old sh before overwrite

        // ---- self-poll full h_t into sh (tag t+1) ----
        {
            const unsigned long long* src = g_hbuf_dec[t & 1];
            S.sh[tid]       = poll_tag(src + tid,       t + 1);
            S.sh[tid + 512] = poll_tag(src + tid + 512, t + 1);
        }
        __syncthreads();

        // ---- phase 2: scores = A @ h (16 per CTA, one warp each), tag t+1 ----
        {
            const float* ar = &S.sA[warp * NH];
            float sacc = 0.f;
            #pragma unroll
            for (int i = 0; i < 32; i++)
                sacc = fmaf(ar[lane + 32 * i], S.sh[lane + 32 * i], sacc);
            #pragma unroll
            for (int o = 16; o > 0; o >>= 1) sacc += __shfl_xor_sync(0xffffffffu, sacc, o);
            if (lane == 0) pub_tag(&g_sbuf[t & 1][c * 16 + warp], sacc, t + 1);
        }

        // ---- phase 3: poll full scores (tag t+1), softmax + context ----
        float sc = poll_tag(&g_sbuf[t & 1][tid], t + 1);
        float mx = sc;
        #pragma unroll
        for (int o = 16; o > 0; o >>= 1) mx = fmaxf(mx, __shfl_xor_sync(0xffffffffu, mx, o));
        if (lane == 0) S.red[warp] = mx;
        __syncthreads();
        if (tid < 16) {
            float v = S.red[tid];
            #pragma unroll
            for (int o = 8; o > 0; o >>= 1) v = fmaxf(v, __shfl_xor_sync(0xffffu, v, o));
            if (tid == 0) S.bc[0] = v;
        }
        __syncthreads();
        float e = __expf(sc - S.bc[0]);
        float sm = e;
        #pragma unroll
        for (int o = 16; o > 0; o >>= 1) sm += __shfl_xor_sync(0xffffffffu, sm, o);
        if (lane == 0) S.red[warp] = sm;
        __syncthreads();
        if (tid < 16) {
            float v = S.red[tid];
            #pragma unroll
            for (int o = 8; o > 0; o >>= 1) v += __shfl_xor_sync(0xffffu, v, o);
            if (tid == 0) S.bc[1] = v;
        }
        __syncthreads();
        float wgt = e / S.bc[1];
        S.sw[tid] = wgt;
        if (c == 0) attns[(size_t)t * ENC + tid] = wgt;
        __syncthreads();

        {
            float ca = 0.f;
            const float* ep = &S.sE[warp * 32 * 32];
            #pragma unroll
            for (int ii = 0; ii < 32; ii++)
                ca = fmaf(S.sw[warp * 32 + ii], ep[ii * 32 + lane], ca);
            S.cred[warp][lane] = ca;
            __syncthreads();
            if (tid < 32) {
                float cs = 0.f;
                #pragma unroll
                for (int g2 = 0; g2 < 16; g2++) cs += S.cred[g2][tid];
                g_hcat[(size_t)t * 2 * NH + NH + c * 32 + tid] = cs;
            }
        }
        __syncthreads();
    }
}

// ---------------- launch ----------------
extern "C" void kernel_launch(void* const* d_in, const int* in_sizes, int n_in,
                              void* d_out, int out_size)
{
    const float* enc_input = (const float*)d_in[0];
    const float* hidden    = (const float*)d_in[1];
    const float* dec_input = (const float*)d_in[2];
    const float* enc_W_ih  = (const float*)d_in[3];
    const float* enc_W_hh  = (const float*)d_in[4];
    const float* enc_b_ih  = (const float*)d_in[5];
    const float* enc_b_hh  = (const float*)d_in[6];
    const float* dec_W_ih  = (const float*)d_in[7];
    const float* dec_W_hh  = (const float*)d_in[8];
    const float* dec_b_ih  = (const float*)d_in[9];
    const float* dec_b_hh  = (const float*)d_in[10];
    const float* attn_W    = (const float*)d_in[11];
    const float* attn_b    = (const float*)d_in[12];
    const float* out_W     = (const float*)d_in[13];
    const float* out_b     = (const float*)d_in[14];

    float* out   = (float*)d_out;
    float* outs  = out;                              // [256, 32000]
    float* attns = out + (size_t)DEC * N_CLASS;      // [256, 512]

    float *p_xw_enc, *p_enc_out, *p_A, *p_xw_dec, *p_hcat, *p_part;
    cudaGetSymbolAddress((void**)&p_xw_enc, g_xw_enc);
    cudaGetSymbolAddress((void**)&p_enc_out, g_enc_out);
    cudaGetSymbolAddress((void**)&p_A, g_A);
    cudaGetSymbolAddress((void**)&p_xw_dec, g_xw_dec);
    cudaGetSymbolAddress((void**)&p_hcat, g_hcat);
    cudaGetSymbolAddress((void**)&p_part, g_part);

    cudaFuncSetAttribute(gemm_mma,
                         cudaFuncAttributeMaxDynamicSharedMemorySize, GEMM_SMEM);
    cudaFuncSetAttribute(dec_scan_kernel,
                         cudaFuncAttributeMaxDynamicSharedMemorySize, (int)sizeof(DecSmem));

    init_kernel<<<8, 256>>>(hidden);

    // enc_xw : M=512,N=1024,K=32000, split 4
    gemm_mma<<<dim3(8, 4, 4), 256, GEMM_SMEM>>>(
        enc_input, enc_W_ih, nullptr, nullptr, p_part, ENC, NH, N_CLASS, 125, 500);
    reduce_splitk<<<(ENC * NH) / 256, 256>>>(p_part, enc_b_ih, p_xw_enc, ENC * NH, NH, 4);

    // dec_xw : M=256,N=1024,K=32000, split 8
    gemm_mma<<<dim3(8, 2, 8), 256, GEMM_SMEM>>>(
        dec_input, dec_W_ih, nullptr, nullptr, p_part, DEC, NH, N_CLASS, 63, 500);
    reduce_splitk<<<(DEC * NH) / 256, 256>>>(p_part, dec_b_ih, p_xw_dec, DEC * NH, NH, 8);

    // encoder scan
    enc_scan_kernel<<<32, 512>>>(enc_W_hh, enc_b_hh);

    // A = enc_out @ attn_W^T + b : direct
    gemm_mma<<<dim3(8, 4, 1), 256, GEMM_SMEM>>>(
        p_enc_out, attn_W, attn_b, p_A, nullptr, ENC, NH, NH, 16, 16);

    // decoder scan
    dec_scan_kernel<<<32, 512, sizeof(DecSmem)>>>(dec_W_hh, dec_b_hh, p_A, attns);

    // outs = hcat @ out_W^T + out_b : direct
    gemm_mma<<<dim3(250, 2, 1), 256, GEMM_SMEM>>>(
        p_hcat, out_W, out_b, outs, nullptr, DEC, N_CLASS, 2 * NH, 32, 32);
}

// round 13
// speedup vs baseline: 2.9069x; 1.0064x over previous
#include <cuda_runtime.h>
#include <cuda_bf16.h>
#include <math.h>
#include <stdint.h>

#define N_CLASS 32000
#define NH      1024
#define ENC     512
#define DEC     256

// ---------------- scratch (no allocations allowed) ----------------
__device__ float g_xw_enc[ENC * NH];
__device__ float g_enc_out[ENC * NH];
__device__ float g_A[ENC * NH];
__device__ float g_xw_dec[DEC * NH];
__device__ float g_hcat[DEC * 2 * NH];
__device__ float g_h0[NH];
__device__ float g_part[8 * 512 * 1024];               // split-K partials (16MB)
__device__ unsigned long long g_hbuf_enc[2][NH];       // {tag<<32 | value} packets
__device__ unsigned long long g_hbuf_dec[2][NH];
__device__ unsigned long long g_sbuf[2][ENC];

// zero tag buffers EVERY launch (graph replays would reuse stale tags)
__global__ void init_kernel(const float* __restrict__ hidden) {
    int i = blockIdx.x * blockDim.x + threadIdx.x;
    if (i < NH) g_h0[i] = hidden[i];
    if (i < 2 * NH) {
        (&g_hbuf_enc[0][0])[i] = 0ULL;
        (&g_hbuf_dec[0][0])[i] = 0ULL;
    }
    if (i < 2 * ENC) (&g_sbuf[0][0])[i] = 0ULL;
}

// ---------------- small helpers ----------------
__device__ __forceinline__ float tanh_fast(float x) {
    float e = __expf(2.f * x);
    return 1.f - 2.f / (e + 1.f);
}
__device__ __forceinline__ unsigned su32(const void* p) {
    return (unsigned)__cvta_generic_to_shared(p);
}
// tagged publish/poll: scalar ALIGNED b64 packet {tag(hi), value(lo)} — single-copy atomic
__device__ __forceinline__ void pub_tag(unsigned long long* p, float v, int tag) {
    unsigned long long pkt = ((unsigned long long)(unsigned)tag << 32)
                           | (unsigned long long)__float_as_uint(v);
    asm volatile("st.relaxed.gpu.global.b64 [%0], %1;" :: "l"(p), "l"(pkt) : "memory");
}
__device__ __forceinline__ float poll_tag(const unsigned long long* p, int tag) {
    unsigned long long pkt;
    do {
        asm volatile("ld.relaxed.gpu.global.b64 %0, [%1];" : "=l"(pkt) : "l"(p) : "memory");
    } while ((unsigned)(pkt >> 32) != (unsigned)tag);
    return __uint_as_float((unsigned)pkt);
}

// ---------------- warp-MMA primitives (generic PTX -> HMMA) ----------------
__device__ __forceinline__ void ldm_x4(unsigned* r, unsigned addr) {
    asm volatile("ldmatrix.sync.aligned.m8n8.x4.shared.b16 {%0,%1,%2,%3}, [%4];"
                 : "=r"(r[0]), "=r"(r[1]), "=r"(r[2]), "=r"(r[3]) : "r"(addr));
}
__device__ __forceinline__ void ldm_x2(unsigned* r, unsigned addr) {
    asm volatile("ldmatrix.sync.aligned.m8n8.x2.shared.b16 {%0,%1}, [%2];"
                 : "=r"(r[0]), "=r"(r[1]) : "r"(addr));
}
__device__ __forceinline__ void mma_bf16(float* d, const unsigned* a, const unsigned* b) {
    asm volatile("mma.sync.aligned.m16n8k16.row.col.f32.bf16.bf16.f32 "
                 "{%0,%1,%2,%3}, {%4,%5,%6,%7}, {%8,%9}, {%0,%1,%2,%3};"
                 : "+f"(d[0]), "+f"(d[1]), "+f"(d[2]), "+f"(d[3])
                 : "r"(a[0]), "r"(a[1]), "r"(a[2]), "r"(a[3]), "r"(b[0]), "r"(b[1]));
}

// ---------------- bf16-split tensor GEMM, software-pipelined (unchanged from R11) ----
#define BK        64
#define PADH      72
#define TILE_B    (128 * PADH * 2)       // 18432
#define STAGE_B   (4 * TILE_B)           // 73728
#define GEMM_SMEM (2 * STAGE_B)          // 147456

__device__ __forceinline__ void ldg_tile(
    const float* __restrict__ src, int K, int row0, long col0, int tid, float4* v)
{
    #pragma unroll
    for (int i = 0; i < 8; i++) {
        int j = tid + 256 * i;
        int r = j >> 4, c = j & 15;
        v[i] = *(const float4*)(src + (size_t)(row0 + r) * K + col0 + c * 4);
    }
}

__device__ __forceinline__ void sts_tile_split(
    const float4* v, unsigned dst_hi, unsigned dst_lo, int tid)
{
    #pragma unroll
    for (int i = 0; i < 8; i++) {
        int j = tid + 256 * i;
        int r = j >> 4, c = j & 15;
        float4 t = v[i];
        __nv_bfloat162 h0 = __floats2bfloat162_rn(t.x, t.y);
        __nv_bfloat162 h1 = __floats2bfloat162_rn(t.z, t.w);
        float lx = t.x - __bfloat162float(h0.x);
        float ly = t.y - __bfloat162float(h0.y);
        float lz = t.z - __bfloat162float(h1.x);
        float lw = t.w - __bfloat162float(h1.y);
        __nv_bfloat162 l0 = __floats2bfloat162_rn(lx, ly);
        __nv_bfloat162 l1 = __floats2bfloat162_rn(lz, lw);
        unsigned boff = (unsigned)(r * PADH + c * 4) * 2;
        unsigned long long hv = ((unsigned long long)(*(unsigned*)&h1) << 32) | (*(unsigned*)&h0);
        unsigned long long lv = ((unsigned long long)(*(unsigned*)&l1) << 32) | (*(unsigned*)&l0);
        asm volatile("st.shared.b64 [%0], %1;" :: "r"(dst_hi + boff), "l"(hv) : "memory");
        asm volatile("st.shared.b64 [%0], %1;" :: "r"(dst_lo + boff), "l"(lv) : "memory");
    }
}

extern __shared__ unsigned char gemm_dyn[];

__global__ void __launch_bounds__(256, 1) gemm_mma(
    const float* __restrict__ Am, const float* __restrict__ Bm,
    const float* __restrict__ bias, float* __restrict__ Cdirect,
    float* __restrict__ partial,
    int M, int N, int K, int kt_per_split, int kt_total)
{
    const unsigned sbase = su32(gemm_dyn);
    const int tid  = threadIdx.x;
    const int wid  = tid >> 5;
    const int lane = tid & 31;
    const int n0 = blockIdx.x * 128;
    const int m0 = blockIdx.y * 128;
    const int s  = blockIdx.z;
    const long kt0 = (long)s * kt_per_split;
    int nt_ = kt_total - (int)kt0;
    if (nt_ > kt_per_split) nt_ = kt_per_split;
    const int ntiles = nt_;

    const int wr = wid >> 2;
    const int wc = wid & 3;

    float acc[4][4][4];
    #pragma unroll
    for (int mt = 0; mt < 4; mt++)
        #pragma unroll
        for (int nt = 0; nt < 4; nt++)
            #pragma unroll
            for (int q = 0; q < 4; q++) acc[mt][nt][q] = 0.f;

    const int arow = wr * 64 + (lane & 15);
    const int acolh = (lane >> 4) * 8;
    const int brow = wc * 32 + (lane & 7);
    const int bcolh = ((lane >> 3) & 1) * 8;

    float4 va[8], vb[8];
    ldg_tile(Am, K, m0, kt0 * BK, tid, va);
    ldg_tile(Bm, K, n0, kt0 * BK, tid, vb);

    for (int kt = 0; kt < ntiles; kt++) {
        const unsigned bb = sbase + (unsigned)(kt & 1) * STAGE_B;
        const unsigned Ah = bb, Al = bb + TILE_B, Bh = bb + 2 * TILE_B, Bl = bb + 3 * TILE_B;

        sts_tile_split(va, Ah, Al, tid);
        sts_tile_split(vb, Bh, Bl, tid);
        __syncthreads();

        if (kt + 1 < ntiles) {
            long c0 = (kt0 + kt + 1) * BK;
            ldg_tile(Am, K, m0, c0, tid, va);
            ldg_tile(Bm, K, n0, c0, tid, vb);
        }

        #pragma unroll
        for (int kk = 0; kk < 4; kk++) {
            unsigned a_hi[4][4], a_lo[4][4], b_hi[4][2], b_lo[4][2];
            #pragma unroll
            for (int mt = 0; mt < 4; mt++) {
                unsigned off = (unsigned)((arow + mt * 16) * PADH + kk * 16 + acolh) * 2;
                ldm_x4(a_hi[mt], Ah + off);
                ldm_x4(a_lo[mt], Al + off);
            }
            #pragma unroll
            for (int nt = 0; nt < 4; nt++) {
                unsigned off = (unsigned)((brow + nt * 8) * PADH + kk * 16 + bcolh) * 2;
                ldm_x2(b_hi[nt], Bh + off);
                ldm_x2(b_lo[nt], Bl + off);
            }
            #pragma unroll
            for (int mt = 0; mt < 4; mt++)
                #pragma unroll
                for (int nt = 0; nt < 4; nt++) {
                    mma_bf16(acc[mt][nt], a_hi[mt], b_hi[nt]);
                    mma_bf16(acc[mt][nt], a_hi[mt], b_lo[nt]);
                    mma_bf16(acc[mt][nt], a_lo[mt], b_hi[nt]);
                }
        }
    }

    const int g   = lane >> 2;
    const int tig = lane & 3;
    if (gridDim.z == 1) {
        #pragma unroll
        for (int mt = 0; mt < 4; mt++) {
            int row = m0 + wr * 64 + mt * 16 + g;
            #pragma unroll
            for (int nt = 0; nt < 4; nt++) {
                int col = n0 + wc * 32 + nt * 8 + tig * 2;
                float b0 = bias[col], b1 = bias[col + 1];
                float2 v0 = {acc[mt][nt][0] + b0, acc[mt][nt][1] + b1};
                float2 v1 = {acc[mt][nt][2] + b0, acc[mt][nt][3] + b1};
                *(float2*)&Cdirect[(size_t)row * N + col] = v0;
                *(float2*)&Cdirect[(size_t)(row + 8) * N + col] = v1;
            }
        }
    } else {
        #pragma unroll
        for (int mt = 0; mt < 4; mt++) {
            int row = m0 + wr * 64 + mt * 16 + g;
            float* pp = partial + ((size_t)s * M + row) * N;
            #pragma unroll
            for (int nt = 0; nt < 4; nt++) {
                int col = n0 + wc * 32 + nt * 8 + tig * 2;
                float2 v0 = {acc[mt][nt][0], acc[mt][nt][1]};
                float2 v1 = {acc[mt][nt][2], acc[mt][nt][3]};
                *(float2*)&pp[col] = v0;
                *(float2*)&pp[(size_t)8 * N + col] = v1;
            }
        }
    }
}

__global__ void reduce_splitk(const float* __restrict__ part,
                              const float* __restrict__ bias,
                              float* __restrict__ C, int MN, int N, int S)
{
    int i = blockIdx.x * 256 + threadIdx.x;
    if (i >= MN) return;
    float a = bias[i & (N - 1)];
    for (int s = 0; s < S; s++) a += part[(size_t)s * MN + i];
    C[i] = a;
}

// ---------------- encoder scan: 2-row h-reuse, rotated conflict-free LDS ----------------
// warp p owns rows {c*32+2p, c*32+2p+1}; lane covers h[lane*32 .. +32) (rotated float4s).
__global__ void __launch_bounds__(512, 1) enc_scan_kernel(
    const float* __restrict__ Whh, const float* __restrict__ bhh)
{
    __shared__ float sh[NH];
    const int c    = blockIdx.x;
    const int tid  = threadIdx.x;
    const int p    = tid >> 5;
    const int lane = tid & 31;
    const int r0   = c * 32 + 2 * p;
    const int r1   = r0 + 1;

    float w0[32], w1[32];
    {
        const float* wp0 = Whh + (size_t)r0 * NH + lane * 32;
        const float* wp1 = Whh + (size_t)r1 * NH + lane * 32;
        #pragma unroll
        for (int j = 0; j < 8; j++) {
            int off = ((j + lane) & 7) * 4;
            #pragma unroll
            for (int k = 0; k < 4; k++) {
                w0[4*j+k] = wp0[off+k];
                w1[4*j+k] = wp1[off+k];
            }
        }
    }
    const float b0 = bhh[r0], b1 = bhh[r1];

    for (int t = 0; t < ENC; t++) {
        // prefetch xw BEFORE polling: latency hides under the spin
        float xw0 = 0.f, xw1 = 0.f;
        if (lane == 0)  xw0 = __ldcg(&g_xw_enc[(size_t)t * NH + r0]);
        if (lane == 16) xw1 = __ldcg(&g_xw_enc[(size_t)t * NH + r1]);

        if (t == 0) {
            if (tid < 256) *(float4*)&sh[tid * 4] = __ldcg((const float4*)g_h0 + tid);
        } else {
            const unsigned long long* src = g_hbuf_enc[(t - 1) & 1];
            sh[tid]       = poll_tag(src + tid,       t);
            sh[tid + 512] = poll_tag(src + tid + 512, t);
        }
        __syncthreads();

        const float* shp = &sh[lane * 32];
        float a0 = 0.f, a1 = 0.f;
        #pragma unroll
        for (int j = 0; j < 8; j++) {
            float4 hv = *(const float4*)&shp[((j + lane) & 7) * 4];
            a0 = fmaf(w0[4*j+0], hv.x, a0); a1 = fmaf(w1[4*j+0], hv.x, a1);
            a0 = fmaf(w0[4*j+1], hv.y, a0); a1 = fmaf(w1[4*j+1], hv.y, a1);
            a0 = fmaf(w0[4*j+2], hv.z, a0); a1 = fmaf(w1[4*j+2], hv.z, a1);
            a0 = fmaf(w0[4*j+3], hv.w, a0); a1 = fmaf(w1[4*j+3], hv.w, a1);
        }
        #pragma unroll
        for (int o = 16; o > 0; o >>= 1) {
            a0 += __shfl_xor_sync(0xffffffffu, a0, o);
            a1 += __shfl_xor_sync(0xffffffffu, a1, o);
        }

        if (lane == 0) {
            float h = tanh_fast(a0 + xw0 + b0);
            g_enc_out[(size_t)t * NH + r0] = h;
            pub_tag(&g_hbuf_enc[t & 1][r0], h, t + 1);
        }
        if (lane == 16) {
            float h = tanh_fast(a1 + xw1 + b1);
            g_enc_out[(size_t)t * NH + r1] = h;
            pub_tag(&g_hbuf_enc[t & 1][r1], h, t + 1);
        }
        __syncthreads();   // protect sh before next step overwrites it
    }
}

// ---------------- decoder scan ----------------
struct DecSmem {
    float sA[16 * NH];
    float sE[ENC * 32];
    float sh[NH];
    float sw[ENC];
    float cred[16][33];
    float red[32];
    float bc[2];
};

extern __shared__ unsigned char dec_dyn[];

__global__ void __launch_bounds__(512, 1) dec_scan_kernel(
    const float* __restrict__ Whh, const float* __restrict__ bhh,
    const float* __restrict__ A, float* __restrict__ attns)
{
    DecSmem& S = *reinterpret_cast<DecSmem*>(dec_dyn);
    const int c    = blockIdx.x;
    const int tid  = threadIdx.x;
    const int p    = tid >> 5;
    const int lane = tid & 31;
    const int warp = p;
    const int r0   = c * 32 + 2 * p;
    const int r1   = r0 + 1;

    float w0[32], w1[32];
    {
        const float* wp0 = Whh + (size_t)r0 * NH + lane * 32;
        const float* wp1 = Whh + (size_t)r1 * NH + lane * 32;
        #pragma unroll
        for (int j = 0; j < 8; j++) {
            int off = ((j + lane) & 7) * 4;
            #pragma unroll
            for (int k = 0; k < 4; k++) {
                w0[4*j+k] = wp0[off+k];
                w1[4*j+k] = wp1[off+k];
            }
        }
    }
    const float b0 = bhh[r0], b1 = bhh[r1];

    for (int idx = tid; idx < 16 * NH; idx += 512)
        S.sA[idx] = A[((size_t)c * 16 + (idx >> 10)) * NH + (idx & (NH - 1))];
    for (int idx = tid; idx < ENC * 32; idx += 512)
        S.sE[idx] = g_enc_out[(size_t)(idx >> 5) * NH + c * 32 + (idx & 31)];
    __syncthreads();

    for (int t = 0; t < DEC; t++) {
        // ---- phase 1: xw prefetch, h_prev poll, matvec (2-row reuse), publish ----
        float xw0 = 0.f, xw1 = 0.f;
        if (lane == 0)  xw0 = __ldcg(&g_xw_dec[(size_t)t * NH + r0]);
        if (lane == 16) xw1 = __ldcg(&g_xw_dec[(size_t)t * NH + r1]);

        if (t == 0) {
            if (tid < 256)
                *(float4*)&S.sh[tid * 4] =
                    __ldcg((const float4*)(g_enc_out + (size_t)(ENC - 1) * NH) + tid);
        } else {
            const unsigned long long* src = g_hbuf_dec[(t - 1) & 1];
            S.sh[tid]       = poll_tag(src + tid,       t);
            S.sh[tid + 512] = poll_tag(src + tid + 512, t);
        }
        __syncthreads();

        {
            const float* shp = &S.sh[lane * 32];
            float a0 = 0.f, a1 = 0.f;
            #pragma unroll
            for (int j = 0; j < 8; j++) {
                float4 hv = *(const float4*)&shp[((j + lane) & 7) * 4];
                a0 = fmaf(w0[4*j+0], hv.x, a0); a1 = fmaf(w1[4*j+0], hv.x, a1);
                a0 = fmaf(w0[4*j+1], hv.y, a0); a1 = fmaf(w1[4*j+1], hv.y, a1);
                a0 = fmaf(w0[4*j+2], hv.z, a0); a1 = fmaf(w1[4*j+2], hv.z, a1);
                a0 = fmaf(w0[4*j+3], hv.w, a0); a1 = fmaf(w1[4*j+3], hv.w, a1);
            }
            #pragma unroll
            for (int o = 16; o > 0; o >>= 1) {
                a0 += __shfl_xor_sync(0xffffffffu, a0, o);
                a1 += __shfl_xor_sync(0xffffffffu, a1, o);
            }
            if (lane == 0) {
                float h = tanh_fast(a0 + xw0 + b0);
                g_hcat[(size_t)t * 2 * NH + r0] = h;
                pub_tag(&g_hbuf_dec[t & 1][r0], h, t + 1);
            }
            if (lane == 16) {
                float h = tanh_fast(a1 + xw1 + b1);
                g_hcat[(size_t)t * 2 * NH + r1] = h;
                pub_tag(&g_hbuf_dec[t & 1][r1], h, t + 1);
            }
        }
        __syncthreads();   // all warps done reading old sh before overwrite

        // ---- self-poll full h_t into sh (tag t+1) ----
        {
            const unsigned long long* src = g_hbuf_dec[t & 1];
            S.sh[tid]       = poll_tag(src + tid,       t + 1);
            S.sh[tid + 512] = poll_tag(src + tid + 512, t + 1);
        }
        __syncthreads();

        // ---- phase 2: scores = A @ h (16 per CTA, one warp each), tag t+1 ----
        {
            const float* ar = &S.sA[warp * NH];
            float sacc = 0.f;
            #pragma unroll
            for (int i = 0; i < 32; i++)
                sacc = fmaf(ar[lane + 32 * i], S.sh[lane + 32 * i], sacc);
            #pragma unroll
            for (int o = 16; o > 0; o >>= 1) sacc += __shfl_xor_sync(0xffffffffu, sacc, o);
            if (lane == 0) pub_tag(&g_sbuf[t & 1][c * 16 + warp], sacc, t + 1);
        }

        // ---- phase 3: poll full scores (tag t+1), softmax + context ----
        float sc = poll_tag(&g_sbuf[t & 1][tid], t + 1);
        float mx = sc;
        #pragma unroll
        for (int o = 16; o > 0; o >>= 1) mx = fmaxf(mx, __shfl_xor_sync(0xffffffffu, mx, o));
        if (lane == 0) S.red[warp] = mx;
        __syncthreads();
        if (tid < 16) {
            float v = S.red[tid];
            #pragma unroll
            for (int o = 8; o > 0; o >>= 1) v = fmaxf(v, __shfl_xor_sync(0xffffu, v, o));
            if (tid == 0) S.bc[0] = v;
        }
        __syncthreads();
        float e = __expf(sc - S.bc[0]);
        float sm = e;
        #pragma unroll
        for (int o = 16; o > 0; o >>= 1) sm += __shfl_xor_sync(0xffffffffu, sm, o);
        if (lane == 0) S.red[warp] = sm;
        __syncthreads();
        if (tid < 16) {
            float v = S.red[tid];
            #pragma unroll
            for (int o = 8; o > 0; o >>= 1) v += __shfl_xor_sync(0xffffu, v, o);
            if (tid == 0) S.bc[1] = v;
        }
        __syncthreads();
        float wgt = e / S.bc[1];
        S.sw[tid] = wgt;
        if (c == 0) attns[(size_t)t * ENC + tid] = wgt;
        __syncthreads();

        {
            float ca = 0.f;
            const float* ep = &S.sE[warp * 32 * 32];
            #pragma unroll
            for (int ii = 0; ii < 32; ii++)
                ca = fmaf(S.sw[warp * 32 + ii], ep[ii * 32 + lane], ca);
            S.cred[warp][lane] = ca;
            __syncthreads();
            if (tid < 32) {
                float cs = 0.f;
                #pragma unroll
                for (int g2 = 0; g2 < 16; g2++) cs += S.cred[g2][tid];
                g_hcat[(size_t)t * 2 * NH + NH + c * 32 + tid] = cs;
            }
        }
        __syncthreads();
    }
}

// ---------------- launch ----------------
extern "C" void kernel_launch(void* const* d_in, const int* in_sizes, int n_in,
                              void* d_out, int out_size)
{
    const float* enc_input = (const float*)d_in[0];
    const float* hidden    = (const float*)d_in[1];
    const float* dec_input = (const float*)d_in[2];
    const float* enc_W_ih  = (const float*)d_in[3];
    const float* enc_W_hh  = (const float*)d_in[4];
    const float* enc_b_ih  = (const float*)d_in[5];
    const float* enc_b_hh  = (const float*)d_in[6];
    const float* dec_W_ih  = (const float*)d_in[7];
    const float* dec_W_hh  = (const float*)d_in[8];
    const float* dec_b_ih  = (const float*)d_in[9];
    const float* dec_b_hh  = (const float*)d_in[10];
    const float* attn_W    = (const float*)d_in[11];
    const float* attn_b    = (const float*)d_in[12];
    const float* out_W     = (const float*)d_in[13];
    const float* out_b     = (const float*)d_in[14];

    float* out   = (float*)d_out;
    float* outs  = out;                              // [256, 32000]
    float* attns = out + (size_t)DEC * N_CLASS;      // [256, 512]

    float *p_xw_enc, *p_enc_out, *p_A, *p_xw_dec, *p_hcat, *p_part;
    cudaGetSymbolAddress((void**)&p_xw_enc, g_xw_enc);
    cudaGetSymbolAddress((void**)&p_enc_out, g_enc_out);
    cudaGetSymbolAddress((void**)&p_A, g_A);
    cudaGetSymbolAddress((void**)&p_xw_dec, g_xw_dec);
    cudaGetSymbolAddress((void**)&p_hcat, g_hcat);
    cudaGetSymbolAddress((void**)&p_part, g_part);

    cudaFuncSetAttribute(gemm_mma,
                         cudaFuncAttributeMaxDynamicSharedMemorySize, GEMM_SMEM);
    cudaFuncSetAttribute(dec_scan_kernel,
                         cudaFuncAttributeMaxDynamicSharedMemorySize, (int)sizeof(DecSmem));

    init_kernel<<<8, 256>>>(hidden);

    // enc_xw : M=512,N=1024,K=32000, split 4
    gemm_mma<<<dim3(8, 4, 4), 256, GEMM_SMEM>>>(
        enc_input, enc_W_ih, nullptr, nullptr, p_part, ENC, NH, N_CLASS, 125, 500);
    reduce_splitk<<<(ENC * NH) / 256, 256>>>(p_part, enc_b_ih, p_xw_enc, ENC * NH, NH, 4);

    // dec_xw : M=256,N=1024,K=32000, split 8
    gemm_mma<<<dim3(8, 2, 8), 256, GEMM_SMEM>>>(
        dec_input, dec_W_ih, nullptr, nullptr, p_part, DEC, NH, N_CLASS, 63, 500);
    reduce_splitk<<<(DEC * NH) / 256, 256>>>(p_part, dec_b_ih, p_xw_dec, DEC * NH, NH, 8);

    // encoder scan
    enc_scan_kernel<<<32, 512>>>(enc_W_hh, enc_b_hh);

    // A = enc_out @ attn_W^T + b : direct
    gemm_mma<<<dim3(8, 4, 1), 256, GEMM_SMEM>>>(
        p_enc_out, attn_W, attn_b, p_A, nullptr, ENC, NH, NH, 16, 16);

    // decoder scan
    dec_scan_kernel<<<32, 512, sizeof(DecSmem)>>>(dec_W_hh, dec_b_hh, p_A, attns);

    // outs = hcat @ out_W^T + out_b : direct
    gemm_mma<<<dim3(250, 2, 1), 256, GEMM_SMEM>>>(
        p_hcat, out_W, out_b, outs, nullptr, DEC, N_CLASS, 2 * NH, 32, 32);
}

// round 14
// speedup vs baseline: 4.6648x; 1.6047x over previous
#include <cuda_runtime.h>
#include <cuda_bf16.h>
#include <math.h>
#include <stdint.h>

#define N_CLASS 32000
#define NH      1024
#define ENC     512
#define DEC     256

// ---------------- scratch (no allocations allowed) ----------------
__device__ float g_xw_enc[ENC * NH];
__device__ float g_enc_out[ENC * NH];
__device__ float g_enc_outT[NH * ENC];                 // transposed copy for ctx GEMM
__device__ float g_A[ENC * NH];
__device__ float g_xw_dec[DEC * NH];
__device__ float g_hcat[DEC * 2 * NH];                 // [h | ctx] rows
__device__ float g_S[DEC * ENC];                       // raw scores
__device__ float g_W[DEC * ENC];                       // softmax weights
__device__ float g_h0[NH];
__device__ float g_zeros[NH];                          // never written: zero bias
__device__ float g_part[8 * 512 * 1024];               // split-K partials (16MB)
__device__ unsigned long long g_hbuf_enc[2][NH];       // {tag<<32 | value} packets
__device__ unsigned long long g_hbuf_dec[2][NH];

// zero tag buffers EVERY launch (graph replays would reuse stale tags)
__global__ void init_kernel(const float* __restrict__ hidden) {
    int i = blockIdx.x * blockDim.x + threadIdx.x;
    if (i < NH) g_h0[i] = hidden[i];
    if (i < 2 * NH) {
        (&g_hbuf_enc[0][0])[i] = 0ULL;
        (&g_hbuf_dec[0][0])[i] = 0ULL;
    }
}

// ---------------- small helpers ----------------
__device__ __forceinline__ float tanh_fast(float x) {
    float e = __expf(2.f * x);
    return 1.f - 2.f / (e + 1.f);
}
__device__ __forceinline__ unsigned su32(const void* p) {
    return (unsigned)__cvta_generic_to_shared(p);
}
// tagged publish/poll: scalar ALIGNED b64 packet {tag(hi), value(lo)} — single-copy atomic
__device__ __forceinline__ void pub_tag(unsigned long long* p, float v, int tag) {
    unsigned long long pkt = ((unsigned long long)(unsigned)tag << 32)
                           | (unsigned long long)__float_as_uint(v);
    asm volatile("st.relaxed.gpu.global.b64 [%0], %1;" :: "l"(p), "l"(pkt) : "memory");
}
// dual poll: both independent loads in flight per retry -> one round trip, not two
__device__ __forceinline__ void poll_tag2(const unsigned long long* p0,
                                          const unsigned long long* p1,
                                          int tag, float& v0, float& v1) {
    unsigned long long a, b;
    const unsigned ut = (unsigned)tag;
    do {
        asm volatile("ld.relaxed.gpu.global.b64 %0, [%1];" : "=l"(a) : "l"(p0) : "memory");
        asm volatile("ld.relaxed.gpu.global.b64 %0, [%1];" : "=l"(b) : "l"(p1) : "memory");
    } while ((unsigned)(a >> 32) != ut || (unsigned)(b >> 32) != ut);
    v0 = __uint_as_float((unsigned)a);
    v1 = __uint_as_float((unsigned)b);
}

// ---------------- warp-MMA primitives (generic PTX -> HMMA) ----------------
__device__ __forceinline__ void ldm_x4(unsigned* r, unsigned addr) {
    asm volatile("ldmatrix.sync.aligned.m8n8.x4.shared.b16 {%0,%1,%2,%3}, [%4];"
                 : "=r"(r[0]), "=r"(r[1]), "=r"(r[2]), "=r"(r[3]) : "r"(addr));
}
__device__ __forceinline__ void ldm_x2(unsigned* r, unsigned addr) {
    asm volatile("ldmatrix.sync.aligned.m8n8.x2.shared.b16 {%0,%1}, [%2];"
                 : "=r"(r[0]), "=r"(r[1]) : "r"(addr));
}
__device__ __forceinline__ void mma_bf16(float* d, const unsigned* a, const unsigned* b) {
    asm volatile("mma.sync.aligned.m16n8k16.row.col.f32.bf16.bf16.f32 "
                 "{%0,%1,%2,%3}, {%4,%5,%6,%7}, {%8,%9}, {%0,%1,%2,%3};"
                 : "+f"(d[0]), "+f"(d[1]), "+f"(d[2]), "+f"(d[3])
                 : "r"(a[0]), "r"(a[1]), "r"(a[2]), "r"(a[3]), "r"(b[0]), "r"(b[1]));
}

// ---------------- bf16-split tensor GEMM, software-pipelined, general strides ------
#define BK        64
#define PADH      72
#define TILE_B    (128 * PADH * 2)       // 18432
#define STAGE_B   (4 * TILE_B)           // 73728
#define GEMM_SMEM (2 * STAGE_B)          // 147456

__device__ __forceinline__ void ldg_tile(
    const float* __restrict__ src, int ld, int row0, long col0, int tid, float4* v)
{
    #pragma unroll
    for (int i = 0; i < 8; i++) {
        int j = tid + 256 * i;
        int r = j >> 4, c = j & 15;
        v[i] = *(const float4*)(src + (size_t)(row0 + r) * ld + col0 + c * 4);
    }
}

__device__ __forceinline__ void sts_tile_split(
    const float4* v, unsigned dst_hi, unsigned dst_lo, int tid)
{
    #pragma unroll
    for (int i = 0; i < 8; i++) {
        int j = tid + 256 * i;
        int r = j >> 4, c = j & 15;
        float4 t = v[i];
        __nv_bfloat162 h0 = __floats2bfloat162_rn(t.x, t.y);
        __nv_bfloat162 h1 = __floats2bfloat162_rn(t.z, t.w);
        float lx = t.x - __bfloat162float(h0.x);
        float ly = t.y - __bfloat162float(h0.y);
        float lz = t.z - __bfloat162float(h1.x);
        float lw = t.w - __bfloat162float(h1.y);
        __nv_bfloat162 l0 = __floats2bfloat162_rn(lx, ly);
        __nv_bfloat162 l1 = __floats2bfloat162_rn(lz, lw);
        unsigned boff = (unsigned)(r * PADH + c * 4) * 2;
        unsigned long long hv = ((unsigned long long)(*(unsigned*)&h1) << 32) | (*(unsigned*)&h0);
        unsigned long long lv = ((unsigned long long)(*(unsigned*)&l1) << 32) | (*(unsigned*)&l0);
        asm volatile("st.shared.b64 [%0], %1;" :: "r"(dst_hi + boff), "l"(hv) : "memory");
        asm volatile("st.shared.b64 [%0], %1;" :: "r"(dst_lo + boff), "l"(lv) : "memory");
    }
}

extern __shared__ unsigned char gemm_dyn[];

__global__ void __launch_bounds__(256, 1) gemm_mma(
    const float* __restrict__ Am, const float* __restrict__ Bm,
    const float* __restrict__ bias, float* __restrict__ Cdirect,
    float* __restrict__ partial,
    int M, int N, int lda, int ldb, int ldc,
    int kt_per_split, int kt_total)
{
    const unsigned sbase = su32(gemm_dyn);
    const int tid  = threadIdx.x;
    const int wid  = tid >> 5;
    const int lane = tid & 31;
    const int n0 = blockIdx.x * 128;
    const int m0 = blockIdx.y * 128;
    const int s  = blockIdx.z;
    const long kt0 = (long)s * kt_per_split;
    int nt_ = kt_total - (int)kt0;
    if (nt_ > kt_per_split) nt_ = kt_per_split;
    const int ntiles = nt_;

    const int wr = wid >> 2;
    const int wc = wid & 3;

    float acc[4][4][4];
    #pragma unroll
    for (int mt = 0; mt < 4; mt++)
        #pragma unroll
        for (int nt = 0; nt < 4; nt++)
            #pragma unroll
            for (int q = 0; q < 4; q++) acc[mt][nt][q] = 0.f;

    const int arow = wr * 64 + (lane & 15);
    const int acolh = (lane >> 4) * 8;
    const int brow = wc * 32 + (lane & 7);
    const int bcolh = ((lane >> 3) & 1) * 8;

    float4 va[8], vb[8];
    ldg_tile(Am, lda, m0, kt0 * BK, tid, va);
    ldg_tile(Bm, ldb, n0, kt0 * BK, tid, vb);

    for (int kt = 0; kt < ntiles; kt++) {
        const unsigned bb = sbase + (unsigned)(kt & 1) * STAGE_B;
        const unsigned Ah = bb, Al = bb + TILE_B, Bh = bb + 2 * TILE_B, Bl = bb + 3 * TILE_B;

        sts_tile_split(va, Ah, Al, tid);
        sts_tile_split(vb, Bh, Bl, tid);
        __syncthreads();

        if (kt + 1 < ntiles) {
            long c0 = (kt0 + kt + 1) * BK;
            ldg_tile(Am, lda, m0, c0, tid, va);
            ldg_tile(Bm, ldb, n0, c0, tid, vb);
        }

        #pragma unroll
        for (int kk = 0; kk < 4; kk++) {
            unsigned a_hi[4][4], a_lo[4][4], b_hi[4][2], b_lo[4][2];
            #pragma unroll
            for (int mt = 0; mt < 4; mt++) {
                unsigned off = (unsigned)((arow + mt * 16) * PADH + kk * 16 + acolh) * 2;
                ldm_x4(a_hi[mt], Ah + off);
                ldm_x4(a_lo[mt], Al + off);
            }
            #pragma unroll
            for (int nt = 0; nt < 4; nt++) {
                unsigned off = (unsigned)((brow + nt * 8) * PADH + kk * 16 + bcolh) * 2;
                ldm_x2(b_hi[nt], Bh + off);
                ldm_x2(b_lo[nt], Bl + off);
            }
            #pragma unroll
            for (int mt = 0; mt < 4; mt++)
                #pragma unroll
                for (int nt = 0; nt < 4; nt++) {
                    mma_bf16(acc[mt][nt], a_hi[mt], b_hi[nt]);
                    mma_bf16(acc[mt][nt], a_hi[mt], b_lo[nt]);
                    mma_bf16(acc[mt][nt], a_lo[mt], b_hi[nt]);
                }
        }
    }

    const int g   = lane >> 2;
    const int tig = lane & 3;
    if (gridDim.z == 1) {
        #pragma unroll
        for (int mt = 0; mt < 4; mt++) {
            int row = m0 + wr * 64 + mt * 16 + g;
            #pragma unroll
            for (int nt = 0; nt < 4; nt++) {
                int col = n0 + wc * 32 + nt * 8 + tig * 2;
                float b0 = bias[col], b1 = bias[col + 1];
                float2 v0 = {acc[mt][nt][0] + b0, acc[mt][nt][1] + b1};
                float2 v1 = {acc[mt][nt][2] + b0, acc[mt][nt][3] + b1};
                *(float2*)&Cdirect[(size_t)row * ldc + col] = v0;
                *(float2*)&Cdirect[(size_t)(row + 8) * ldc + col] = v1;
            }
        }
    } else {
        #pragma unroll
        for (int mt = 0; mt < 4; mt++) {
            int row = m0 + wr * 64 + mt * 16 + g;
            float* pp = partial + ((size_t)s * M + row) * N;
            #pragma unroll
            for (int nt = 0; nt < 4; nt++) {
                int col = n0 + wc * 32 + nt * 8 + tig * 2;
                float2 v0 = {acc[mt][nt][0], acc[mt][nt][1]};
                float2 v1 = {acc[mt][nt][2], acc[mt][nt][3]};
                *(float2*)&pp[col] = v0;
                *(float2*)&pp[(size_t)8 * N + col] = v1;
            }
        }
    }
}

__global__ void reduce_splitk(const float* __restrict__ part,
                              const float* __restrict__ bias,
                              float* __restrict__ C, int MN, int N, int S)
{
    int i = blockIdx.x * 256 + threadIdx.x;
    if (i >= MN) return;
    float a = bias[i & (N - 1)];
    for (int s = 0; s < S; s++) a += part[(size_t)s * MN + i];
    C[i] = a;
}

// ---------------- encoder scan: 2-row h-reuse, dual-poll ----------------
__global__ void __launch_bounds__(512, 1) enc_scan_kernel(
    const float* __restrict__ Whh, const float* __restrict__ bhh)
{
    __shared__ float sh[NH];
    const int c    = blockIdx.x;
    const int tid  = threadIdx.x;
    const int p    = tid >> 5;
    const int lane = tid & 31;
    const int r0   = c * 32 + 2 * p;
    const int r1   = r0 + 1;

    float w0[32], w1[32];
    {
        const float* wp0 = Whh + (size_t)r0 * NH + lane * 32;
        const float* wp1 = Whh + (size_t)r1 * NH + lane * 32;
        #pragma unroll
        for (int j = 0; j < 8; j++) {
            int off = ((j + lane) & 7) * 4;
            #pragma unroll
            for (int k = 0; k < 4; k++) {
                w0[4*j+k] = wp0[off+k];
                w1[4*j+k] = wp1[off+k];
            }
        }
    }
    const float b0 = bhh[r0], b1 = bhh[r1];

    for (int t = 0; t < ENC; t++) {
        float xw0 = 0.f, xw1 = 0.f;
        if (lane == 0)  xw0 = __ldcg(&g_xw_enc[(size_t)t * NH + r0]);
        if (lane == 16) xw1 = __ldcg(&g_xw_enc[(size_t)t * NH + r1]);

        if (t == 0) {
            if (tid < 256) *(float4*)&sh[tid * 4] = __ldcg((const float4*)g_h0 + tid);
        } else {
            const unsigned long long* src = g_hbuf_enc[(t - 1) & 1];
            float v0, v1;
            poll_tag2(src + tid, src + tid + 512, t, v0, v1);
            sh[tid] = v0; sh[tid + 512] = v1;
        }
        __syncthreads();

        const float* shp = &sh[lane * 32];
        float a0 = 0.f, a1 = 0.f;
        #pragma unroll
        for (int j = 0; j < 8; j++) {
            float4 hv = *(const float4*)&shp[((j + lane) & 7) * 4];
            a0 = fmaf(w0[4*j+0], hv.x, a0); a1 = fmaf(w1[4*j+0], hv.x, a1);
            a0 = fmaf(w0[4*j+1], hv.y, a0); a1 = fmaf(w1[4*j+1], hv.y, a1);
            a0 = fmaf(w0[4*j+2], hv.z, a0); a1 = fmaf(w1[4*j+2], hv.z, a1);
            a0 = fmaf(w0[4*j+3], hv.w, a0); a1 = fmaf(w1[4*j+3], hv.w, a1);
        }
        #pragma unroll
        for (int o = 16; o > 0; o >>= 1) {
            a0 += __shfl_xor_sync(0xffffffffu, a0, o);
            a1 += __shfl_xor_sync(0xffffffffu, a1, o);
        }

        if (lane == 0) {
            float h = tanh_fast(a0 + xw0 + b0);
            pub_tag(&g_hbuf_enc[t & 1][r0], h, t + 1);
            g_enc_out[(size_t)t * NH + r0]  = h;
            g_enc_outT[(size_t)r0 * ENC + t] = h;
        }
        if (lane == 16) {
            float h = tanh_fast(a1 + xw1 + b1);
            pub_tag(&g_hbuf_enc[t & 1][r1], h, t + 1);
            g_enc_out[(size_t)t * NH + r1]  = h;
            g_enc_outT[(size_t)r1 * ENC + t] = h;
        }
        __syncthreads();
    }
}

// ---------------- decoder scan: PURE h chain (attention hoisted to GEMMs) ----------
__global__ void __launch_bounds__(512, 1) dec_scan_kernel(
    const float* __restrict__ Whh, const float* __restrict__ bhh)
{
    __shared__ float sh[NH];
    const int c    = blockIdx.x;
    const int tid  = threadIdx.x;
    const int p    = tid >> 5;
    const int lane = tid & 31;
    const int r0   = c * 32 + 2 * p;
    const int r1   = r0 + 1;

    float w0[32], w1[32];
    {
        const float* wp0 = Whh + (size_t)r0 * NH + lane * 32;
        const float* wp1 = Whh + (size_t)r1 * NH + lane * 32;
        #pragma unroll
        for (int j = 0; j < 8; j++) {
            int off = ((j + lane) & 7) * 4;
            #pragma unroll
            for (int k = 0; k < 4; k++) {
                w0[4*j+k] = wp0[off+k];
                w1[4*j+k] = wp1[off+k];
            }
        }
    }
    const float b0 = bhh[r0], b1 = bhh[r1];

    for (int t = 0; t < DEC; t++) {
        float xw0 = 0.f, xw1 = 0.f;
        if (lane == 0)  xw0 = __ldcg(&g_xw_dec[(size_t)t * NH + r0]);
        if (lane == 16) xw1 = __ldcg(&g_xw_dec[(size_t)t * NH + r1]);

        if (t == 0) {
            if (tid < 256)
                *(float4*)&sh[tid * 4] =
                    __ldcg((const float4*)(g_enc_out + (size_t)(ENC - 1) * NH) + tid);
        } else {
            const unsigned long long* src = g_hbuf_dec[(t - 1) & 1];
            float v0, v1;
            poll_tag2(src + tid, src + tid + 512, t, v0, v1);
            sh[tid] = v0; sh[tid + 512] = v1;
        }
        __syncthreads();

        const float* shp = &sh[lane * 32];
        float a0 = 0.f, a1 = 0.f;
        #pragma unroll
        for (int j = 0; j < 8; j++) {
            float4 hv = *(const float4*)&shp[((j + lane) & 7) * 4];
            a0 = fmaf(w0[4*j+0], hv.x, a0); a1 = fmaf(w1[4*j+0], hv.x, a1);
            a0 = fmaf(w0[4*j+1], hv.y, a0); a1 = fmaf(w1[4*j+1], hv.y, a1);
            a0 = fmaf(w0[4*j+2], hv.z, a0); a1 = fmaf(w1[4*j+2], hv.z, a1);
            a0 = fmaf(w0[4*j+3], hv.w, a0); a1 = fmaf(w1[4*j+3], hv.w, a1);
        }
        #pragma unroll
        for (int o = 16; o > 0; o >>= 1) {
            a0 += __shfl_xor_sync(0xffffffffu, a0, o);
            a1 += __shfl_xor_sync(0xffffffffu, a1, o);
        }

        if (lane == 0) {
            float h = tanh_fast(a0 + xw0 + b0);
            pub_tag(&g_hbuf_dec[t & 1][r0], h, t + 1);
            g_hcat[(size_t)t * 2 * NH + r0] = h;
        }
        if (lane == 16) {
            float h = tanh_fast(a1 + xw1 + b1);
            pub_tag(&g_hbuf_dec[t & 1][r1], h, t + 1);
            g_hcat[(size_t)t * 2 * NH + r1] = h;
        }
        __syncthreads();
    }
}

// ---------------- batched row softmax over S[256,512] ----------------
__global__ void __launch_bounds__(512) softmax_kernel(float* __restrict__ attns)
{
    __shared__ float red[16];
    __shared__ float bc[2];
    const int t = blockIdx.x, tid = threadIdx.x, warp = tid >> 5, lane = tid & 31;

    float sc = g_S[(size_t)t * ENC + tid];
    float mx = sc;
    #pragma unroll
    for (int o = 16; o > 0; o >>= 1) mx = fmaxf(mx, __shfl_xor_sync(0xffffffffu, mx, o));
    if (lane == 0) red[warp] = mx;
    __syncthreads();
    if (tid < 16) {
        float v = red[tid];
        #pragma unroll
        for (int o = 8; o > 0; o >>= 1) v = fmaxf(v, __shfl_xor_sync(0xffffu, v, o));
        if (tid == 0) bc[0] = v;
    }
    __syncthreads();
    float e = __expf(sc - bc[0]);
    float sm = e;
    #pragma unroll
    for (int o = 16; o > 0; o >>= 1) sm += __shfl_xor_sync(0xffffffffu, sm, o);
    if (lane == 0) red[warp] = sm;
    __syncthreads();
    if (tid < 16) {
        float v = red[tid];
        #pragma unroll
        for (int o = 8; o > 0; o >>= 1) v += __shfl_xor_sync(0xffffu, v, o);
        if (tid == 0) bc[1] = v;
    }
    __syncthreads();
    float w = e / bc[1];
    g_W[(size_t)t * ENC + tid] = w;
    attns[(size_t)t * ENC + tid] = w;
}

// ---------------- launch ----------------
extern "C" void kernel_launch(void* const* d_in, const int* in_sizes, int n_in,
                              void* d_out, int out_size)
{
    const float* enc_input = (const float*)d_in[0];
    const float* hidden    = (const float*)d_in[1];
    const float* dec_input = (const float*)d_in[2];
    const float* enc_W_ih  = (const float*)d_in[3];
    const float* enc_W_hh  = (const float*)d_in[4];
    const float* enc_b_ih  = (const float*)d_in[5];
    const float* enc_b_hh  = (const float*)d_in[6];
    const float* dec_W_ih  = (const float*)d_in[7];
    const float* dec_W_hh  = (const float*)d_in[8];
    const float* dec_b_ih  = (const float*)d_in[9];
    const float* dec_b_hh  = (const float*)d_in[10];
    const float* attn_W    = (const float*)d_in[11];
    const float* attn_b    = (const float*)d_in[12];
    const float* out_W     = (const float*)d_in[13];
    const float* out_b     = (const float*)d_in[14];

    float* out   = (float*)d_out;
    float* outs  = out;                              // [256, 32000]
    float* attns = out + (size_t)DEC * N_CLASS;      // [256, 512]

    float *p_xw_enc, *p_enc_out, *p_enc_outT, *p_A, *p_xw_dec, *p_hcat,
          *p_S, *p_W, *p_part, *p_zeros;
    cudaGetSymbolAddress((void**)&p_xw_enc, g_xw_enc);
    cudaGetSymbolAddress((void**)&p_enc_out, g_enc_out);
    cudaGetSymbolAddress((void**)&p_enc_outT, g_enc_outT);
    cudaGetSymbolAddress((void**)&p_A, g_A);
    cudaGetSymbolAddress((void**)&p_xw_dec, g_xw_dec);
    cudaGetSymbolAddress((void**)&p_hcat, g_hcat);
    cudaGetSymbolAddress((void**)&p_S, g_S);
    cudaGetSymbolAddress((void**)&p_W, g_W);
    cudaGetSymbolAddress((void**)&p_part, g_part);
    cudaGetSymbolAddress((void**)&p_zeros, g_zeros);

    cudaFuncSetAttribute(gemm_mma,
                         cudaFuncAttributeMaxDynamicSharedMemorySize, GEMM_SMEM);

    init_kernel<<<8, 256>>>(hidden);

    // enc_xw : M=512,N=1024,K=32000, split 4
    gemm_mma<<<dim3(8, 4, 4), 256, GEMM_SMEM>>>(
        enc_input, enc_W_ih, nullptr, nullptr, p_part,
        ENC, NH, N_CLASS, N_CLASS, 0, 125, 500);
    reduce_splitk<<<(ENC * NH) / 256, 256>>>(p_part, enc_b_ih, p_xw_enc, ENC * NH, NH, 4);

    // dec_xw : M=256,N=1024,K=32000, split 8
    gemm_mma<<<dim3(8, 2, 8), 256, GEMM_SMEM>>>(
        dec_input, dec_W_ih, nullptr, nullptr, p_part,
        DEC, NH, N_CLASS, N_CLASS, 0, 63, 500);
    reduce_splitk<<<(DEC * NH) / 256, 256>>>(p_part, dec_b_ih, p_xw_dec, DEC * NH, NH, 8);

    // encoder scan (writes g_enc_out + g_enc_outT)
    enc_scan_kernel<<<32, 512>>>(enc_W_hh, enc_b_hh);

    // A = enc_out @ attn_W^T + b : M=512,N=1024,K=1024 direct
    gemm_mma<<<dim3(8, 4, 1), 256, GEMM_SMEM>>>(
        p_enc_out, attn_W, attn_b, p_A, nullptr,
        ENC, NH, NH, NH, NH, 16, 16);

    // decoder scan: pure h chain -> g_hcat[:, :NH]
    dec_scan_kernel<<<32, 512>>>(dec_W_hh, dec_b_hh);

    // S = H @ A^T : M=256,N=512,K=1024 (A rows = g_hcat stride 2048)
    gemm_mma<<<dim3(4, 2, 1), 256, GEMM_SMEM>>>(
        p_hcat, p_A, p_zeros, p_S, nullptr,
        DEC, ENC, 2 * NH, NH, ENC, 16, 16);

    // row softmax -> g_W + attns
    softmax_kernel<<<DEC, 512>>>(attns);

    // ctx = W @ enc_out : M=256,N=1024,K=512 (B = enc_outT), C into g_hcat[:, NH:]
    gemm_mma<<<dim3(8, 2, 1), 256, GEMM_SMEM>>>(
        p_W, p_enc_outT, p_zeros, p_hcat + NH, nullptr,
        DEC, NH, ENC, ENC, 2 * NH, 8, 8);

    // outs = hcat @ out_W^T + out_b : M=256,N=32000,K=2048 direct
    gemm_mma<<<dim3(250, 2, 1), 256, GEMM_SMEM>>>(
        p_hcat, out_W, out_b, outs, nullptr,
        DEC, N_CLASS, 2 * NH, 2 * NH, N_CLASS, 32, 32);
}